// round 1
// baseline (speedup 1.0000x reference)
#include <cuda_runtime.h>
#include <cuda_bf16.h>

#define N_FEAT   256
#define BATCH    8192
#define CLASSES  5
#define EDGES    500000
#define D_CONV   128
#define D_EMB    256
#define SEGS     10          // 2 sides * 5 classes
#define BN_EPS   1e-3f

// ---------------- scratch (static device globals; no runtime allocation) ----
__device__ int   g_cnt [SEGS * BATCH];          // histogram, then cursor, then bucket-end
__device__ int   g_off [SEGS * BATCH];          // exclusive offsets (bucket start)
__device__ int   g_ssrc[SEGS * EDGES];          // sorted edge src
__device__ float g_sw  [SEGS * EDGES];          // sorted edge weight
__device__ float g_agg [SEGS * BATCH * N_FEAT]; // aggregated features per seg  (~84 MB)
__device__ float g_f   [2 * BATCH * N_FEAT];    // f_user / f_item (post BN+relu)
__device__ float g_h   [2 * BATCH * CLASSES * D_CONV]; // h_user/h_item (post BN+relu)
__device__ float g_tmp [2 * BATCH * D_EMB];     // emb partial (f @ W2_f)
__device__ float g_emb [2 * BATCH * D_EMB];     // user_emb / item_emb
__device__ float g_t   [2 * BATCH * D_EMB];     // decoder temps t0, t1

// ---------------- counting sort of edges by dst, per segment ----------------
__global__ void zero_cnt_kernel() {
    int i = blockIdx.x * 256 + threadIdx.x;
    if (i < SEGS * BATCH) g_cnt[i] = 0;
}

__global__ void hist_kernel(const int* __restrict__ udst, const int* __restrict__ idst) {
    int i = blockIdx.x * 256 + threadIdx.x;
    if (i >= SEGS * EDGES) return;
    int seg = i / EDGES, e = i - seg * EDGES;
    int dst = (seg < CLASSES) ? udst[seg * EDGES + e] : idst[(seg - CLASSES) * EDGES + e];
    atomicAdd(&g_cnt[seg * BATCH + dst], 1);
}

// one block per segment: exclusive scan of 8192 counts -> g_off, init cursor in g_cnt
__global__ void scan_kernel() {
    int seg = blockIdx.x;
    int t = threadIdx.x;                 // 1024 threads, 8 bins each
    int base = seg * BATCH + t * 8;
    int v[8], s = 0;
#pragma unroll
    for (int j = 0; j < 8; j++) { v[j] = g_cnt[base + j]; s += v[j]; }
    __shared__ int sh[1024];
    sh[t] = s;
    __syncthreads();
    for (int off = 1; off < 1024; off <<= 1) {
        int x = (t >= off) ? sh[t - off] : 0;
        __syncthreads();
        sh[t] += x;
        __syncthreads();
    }
    int run = sh[t] - s;                 // exclusive prefix
#pragma unroll
    for (int j = 0; j < 8; j++) {
        g_off[base + j] = run;
        g_cnt[base + j] = run;           // cursor starts at offset
        run += v[j];
    }
}

__global__ void scatter_kernel(const int* __restrict__ usrc, const int* __restrict__ udst,
                               const float* __restrict__ uw,
                               const int* __restrict__ isrc, const int* __restrict__ idst,
                               const float* __restrict__ iw) {
    int i = blockIdx.x * 256 + threadIdx.x;
    if (i >= SEGS * EDGES) return;
    int seg = i / EDGES, e = i - seg * EDGES;
    int src, dst; float w;
    if (seg < CLASSES) {
        int o = seg * EDGES + e;
        src = usrc[o]; dst = udst[o]; w = uw[o];
    } else {
        int o = (seg - CLASSES) * EDGES + e;
        src = isrc[o]; dst = idst[o]; w = iw[o];
    }
    int pos = atomicAdd(&g_cnt[seg * BATCH + dst], 1);
    g_ssrc[seg * EDGES + pos] = src;
    g_sw  [seg * EDGES + pos] = w;
}

// one block (256 thr) per (dst, seg); thread owns one feature column
__global__ void agg_kernel(const float* __restrict__ user_feat,
                           const float* __restrict__ item_feat) {
    int dst = blockIdx.x;
    int seg = blockIdx.y;
    int tid = threadIdx.x;
    const float* feat = (seg < CLASSES) ? item_feat : user_feat;  // aggregate opposite side
    int start = g_off[seg * BATCH + dst];
    int end   = g_cnt[seg * BATCH + dst];   // cursor final = start + count
    const int*   ss = g_ssrc + seg * EDGES;
    const float* sw = g_sw   + seg * EDGES;
    float acc = 0.f;
    int e = start;
    for (; e + 4 <= end; e += 4) {
        int   s0 = ss[e],   s1 = ss[e+1], s2 = ss[e+2], s3 = ss[e+3];
        float w0 = sw[e],   w1 = sw[e+1], w2 = sw[e+2], w3 = sw[e+3];
        float v0 = feat[(long)s0 * N_FEAT + tid];
        float v1 = feat[(long)s1 * N_FEAT + tid];
        float v2 = feat[(long)s2 * N_FEAT + tid];
        float v3 = feat[(long)s3 * N_FEAT + tid];
        acc += w0 * v0 + w1 * v1 + w2 * v2 + w3 * v3;
    }
    for (; e < end; e++)
        acc += sw[e] * feat[(long)ss[e] * N_FEAT + tid];
    g_agg[((long)seg * BATCH + dst) * N_FEAT + tid] = acc;
}

// ---------------- tiled SGEMM: C[M,N] = act(A[M,K] @ B[K,N] + ...) ----------
// EPI: 0 = none, 1 = bias + BN + relu, 2 = BN + relu, 3 = add(addend) + relu
// M multiple of 64, N multiple of 64, K multiple of 16 (all shapes here comply)
template<int EPI>
__global__ void sgemm_kernel(const float* __restrict__ A, const int* __restrict__ gidx, int lda,
                             const float* __restrict__ B, int ldb,
                             float* __restrict__ C, int ldc, int col0,
                             int K,
                             const float* __restrict__ bias,
                             const float* __restrict__ bnp, int bn_dim,
                             const float* __restrict__ addend, int ldadd) {
    __shared__ float As[16][64];
    __shared__ float Bs[16][64];
    int m0 = blockIdx.y * 64;
    int n0 = blockIdx.x * 64;
    int tid = threadIdx.x;
    int tx = tid & 15, ty = tid >> 4;
    int arow = tid >> 2;            // 0..63
    int ak4  = (tid & 3) * 4;       // 0,4,8,12
    int brow = tid >> 4;            // 0..15
    int bn4  = (tid & 15) * 4;

    const float* Arow_ptr;
    {
        int gr = m0 + arow;
        int r  = gidx ? gidx[gr] : gr;
        Arow_ptr = A + (long)r * lda;
    }

    float acc[4][4];
#pragma unroll
    for (int i = 0; i < 4; i++)
#pragma unroll
        for (int j = 0; j < 4; j++) acc[i][j] = 0.f;

    for (int k0 = 0; k0 < K; k0 += 16) {
        float4 av = *(const float4*)(Arow_ptr + k0 + ak4);
        float4 bv = *(const float4*)(B + (long)(k0 + brow) * ldb + n0 + bn4);
        __syncthreads();
        As[ak4 + 0][arow] = av.x;
        As[ak4 + 1][arow] = av.y;
        As[ak4 + 2][arow] = av.z;
        As[ak4 + 3][arow] = av.w;
        *(float4*)(&Bs[brow][bn4]) = bv;
        __syncthreads();
#pragma unroll
        for (int kk = 0; kk < 16; kk++) {
            float4 a = *(const float4*)(&As[kk][ty * 4]);
            float4 b = *(const float4*)(&Bs[kk][tx * 4]);
            float ar[4] = {a.x, a.y, a.z, a.w};
            float br[4] = {b.x, b.y, b.z, b.w};
#pragma unroll
            for (int i = 0; i < 4; i++)
#pragma unroll
                for (int j = 0; j < 4; j++)
                    acc[i][j] += ar[i] * br[j];
        }
    }

#pragma unroll
    for (int i = 0; i < 4; i++) {
        int r = m0 + ty * 4 + i;
#pragma unroll
        for (int j = 0; j < 4; j++) {
            int c  = n0 + tx * 4 + j;
            int cg = col0 + c;
            float x = acc[i][j];
            if (EPI == 1) x += bias[c];
            if (EPI == 1 || EPI == 2) {
                float gma  = bnp[cg];
                float beta = bnp[bn_dim + cg];
                float mean = bnp[2 * bn_dim + cg];
                float var  = bnp[3 * bn_dim + cg];
                x = gma * (x - mean) * rsqrtf(var + BN_EPS) + beta;
                x = fmaxf(x, 0.f);
            }
            if (EPI == 3) {
                x += addend[(long)r * ldadd + cg];
                x = fmaxf(x, 0.f);
            }
            C[(long)r * ldc + cg] = x;
        }
    }
}

// ---------------- bilinear decoder combine ----------------------------------
// logits[b,r] = sum_k Wcomb[r,k] * dot(t_k[b,:], item_emb[b,:])
__global__ void decode_kernel(const float* __restrict__ t0, const float* __restrict__ t1,
                              const float* __restrict__ ve, const float* __restrict__ Wcomb,
                              float* __restrict__ out) {
    int b = blockIdx.x, t = threadIdx.x;  // 256 threads
    float v  = ve[(long)b * D_EMB + t];
    float a0 = t0[(long)b * D_EMB + t] * v;
    float a1 = t1[(long)b * D_EMB + t] * v;
#pragma unroll
    for (int o = 16; o; o >>= 1) {
        a0 += __shfl_down_sync(0xffffffffu, a0, o);
        a1 += __shfl_down_sync(0xffffffffu, a1, o);
    }
    __shared__ float s0[8], s1[8];
    if ((t & 31) == 0) { s0[t >> 5] = a0; s1[t >> 5] = a1; }
    __syncthreads();
    if (t == 0) {
        float d0 = 0.f, d1 = 0.f;
#pragma unroll
        for (int i = 0; i < 8; i++) { d0 += s0[i]; d1 += s1[i]; }
        s0[0] = d0; s1[0] = d1;
    }
    __syncthreads();
    if (t < CLASSES)
        out[(long)b * CLASSES + t] = Wcomb[t * 2] * s0[0] + Wcomb[t * 2 + 1] * s1[0];
}

// ---------------- launch ----------------------------------------------------
extern "C" void kernel_launch(void* const* d_in, const int* in_sizes, int n_in,
                              void* d_out, int out_size) {
    const float* user_feat = (const float*)d_in[0];
    const float* item_feat = (const float*)d_in[1];
    const int*   user_idx  = (const int*)d_in[2];
    const int*   item_idx  = (const int*)d_in[3];
    const int*   u_src     = (const int*)d_in[4];
    const int*   u_dst     = (const int*)d_in[5];
    const float* u_w       = (const float*)d_in[6];
    const int*   i_src     = (const int*)d_in[7];
    const int*   i_dst     = (const int*)d_in[8];
    const float* i_w       = (const float*)d_in[9];
    const float* W_fu      = (const float*)d_in[10];
    const float* b_fu      = (const float*)d_in[11];
    const float* W_fi      = (const float*)d_in[12];
    const float* b_fi      = (const float*)d_in[13];
    const float* W_uc      = (const float*)d_in[14];
    const float* W_ic      = (const float*)d_in[15];
    const float* bn_fu     = (const float*)d_in[16];
    const float* bn_hu     = (const float*)d_in[17];
    const float* bn_fi     = (const float*)d_in[18];
    const float* bn_hi     = (const float*)d_in[19];
    const float* W2_fu     = (const float*)d_in[20];
    const float* W2_hu     = (const float*)d_in[21];
    const float* W2_fi     = (const float*)d_in[22];
    const float* W2_hi     = (const float*)d_in[23];
    const float* Wdec      = (const float*)d_in[24];
    const float* Wcomb     = (const float*)d_in[25];
    float* out = (float*)d_out;

    void* p;
    cudaGetSymbolAddress(&p, g_agg); float* agg  = (float*)p;
    cudaGetSymbolAddress(&p, g_f);   float* fb   = (float*)p;
    cudaGetSymbolAddress(&p, g_h);   float* hb   = (float*)p;
    cudaGetSymbolAddress(&p, g_tmp); float* tmp  = (float*)p;
    cudaGetSymbolAddress(&p, g_emb); float* emb  = (float*)p;
    cudaGetSymbolAddress(&p, g_t);   float* tdec = (float*)p;

    const int HD = CLASSES * D_CONV;  // 640

    // 1) edge counting-sort by dst (per segment)
    zero_cnt_kernel<<<(SEGS * BATCH + 255) / 256, 256>>>();
    int eblocks = (SEGS * EDGES + 255) / 256;
    hist_kernel<<<eblocks, 256>>>(u_dst, i_dst);
    scan_kernel<<<SEGS, 1024>>>();
    scatter_kernel<<<eblocks, 256>>>(u_src, u_dst, u_w, i_src, i_dst, i_w);

    // 2) per-bucket weighted aggregation (no float atomics)
    agg_kernel<<<dim3(BATCH, SEGS), 256>>>(user_feat, item_feat);

    // 3) f projections: gather rows + GEMM + bias + BN + relu
    sgemm_kernel<1><<<dim3(4, 128), 256>>>(user_feat, user_idx, N_FEAT, W_fu, 256,
                                           fb, 256, 0, N_FEAT, b_fu, bn_fu, 256, nullptr, 0);
    sgemm_kernel<1><<<dim3(4, 128), 256>>>(item_feat, item_idx, N_FEAT, W_fi, 256,
                                           fb + (long)BATCH * 256, 256, 0, N_FEAT,
                                           b_fi, bn_fi, 256, nullptr, 0);

    // 4) per-class projections of aggregated features + BN + relu
    for (int seg = 0; seg < SEGS; seg++) {
        int side = seg / CLASSES, c = seg % CLASSES;
        const float* Bm = (side ? W_ic : W_uc) + (long)c * N_FEAT * D_CONV;
        const float* bn = side ? bn_hi : bn_hu;
        float* Cm = hb + (long)side * BATCH * HD;
        sgemm_kernel<2><<<dim3(2, 128), 256>>>(agg + (long)seg * BATCH * N_FEAT, nullptr, N_FEAT,
                                               Bm, D_CONV, Cm, HD, c * D_CONV, N_FEAT,
                                               nullptr, bn, HD, nullptr, 0);
    }

    // 5) embeddings: emb = relu(f @ W2_f + h @ W2_h)
    for (int side = 0; side < 2; side++) {
        const float* W2f = side ? W2_fi : W2_fu;
        const float* W2h = side ? W2_hi : W2_hu;
        float* f_s  = fb  + (long)side * BATCH * 256;
        float* h_s  = hb  + (long)side * BATCH * HD;
        float* tp   = tmp + (long)side * BATCH * D_EMB;
        float* em   = emb + (long)side * BATCH * D_EMB;
        sgemm_kernel<0><<<dim3(4, 128), 256>>>(f_s, nullptr, 256, W2f, D_EMB,
                                               tp, D_EMB, 0, 256, nullptr, nullptr, 0, nullptr, 0);
        sgemm_kernel<3><<<dim3(4, 128), 256>>>(h_s, nullptr, HD, W2h, D_EMB,
                                               em, D_EMB, 0, HD, nullptr, nullptr, 0, tp, D_EMB);
    }

    // 6) bilinear decoder: t_k = user_emb @ Wdec[k]; combine with item_emb
    float* uemb = emb;
    float* iemb = emb + (long)BATCH * D_EMB;
    sgemm_kernel<0><<<dim3(4, 128), 256>>>(uemb, nullptr, D_EMB, Wdec, D_EMB,
                                           tdec, D_EMB, 0, D_EMB, nullptr, nullptr, 0, nullptr, 0);
    sgemm_kernel<0><<<dim3(4, 128), 256>>>(uemb, nullptr, D_EMB, Wdec + D_EMB * D_EMB, D_EMB,
                                           tdec + (long)BATCH * D_EMB, D_EMB, 0, D_EMB,
                                           nullptr, nullptr, 0, nullptr, 0);
    decode_kernel<<<BATCH, 256>>>(tdec, tdec + (long)BATCH * D_EMB, iemb, Wcomb, out);
}

// round 2
// speedup vs baseline: 1.5894x; 1.5894x over previous
#include <cuda_runtime.h>
#include <cuda_bf16.h>

#define N_FEAT   256
#define BATCH    8192
#define CLASSES  5
#define EDGES    500000
#define D_CONV   128
#define D_EMB    256
#define SEGS     10          // 2 sides * 5 classes
#define BN_EPS   1e-3f

// ---------------- scratch (static device globals; no runtime allocation) ----
__device__ int   g_cnt [SEGS * BATCH];
__device__ int   g_off [SEGS * BATCH];
__device__ int   g_ssrc[SEGS * EDGES];
__device__ float g_sw  [SEGS * EDGES];
__device__ float g_agg [SEGS * BATCH * N_FEAT];
__device__ float g_f   [2 * BATCH * N_FEAT];
__device__ float g_h   [2 * BATCH * CLASSES * D_CONV];
__device__ float g_tmp [2 * BATCH * D_EMB];
__device__ float g_emb [2 * BATCH * D_EMB];
__device__ float g_t   [2 * BATCH * D_EMB];

// ---------------- counting sort of edges by dst, per segment ----------------
__global__ void zero_cnt_kernel() {
    int i = blockIdx.x * 256 + threadIdx.x;
    if (i < SEGS * BATCH) g_cnt[i] = 0;
}

__global__ void hist_kernel(const int* __restrict__ udst, const int* __restrict__ idst) {
    int i = blockIdx.x * 256 + threadIdx.x;
    if (i >= SEGS * EDGES) return;
    int seg = i / EDGES, e = i - seg * EDGES;
    int dst = (seg < CLASSES) ? udst[seg * EDGES + e] : idst[(seg - CLASSES) * EDGES + e];
    atomicAdd(&g_cnt[seg * BATCH + dst], 1);
}

__global__ void scan_kernel() {
    int seg = blockIdx.x;
    int t = threadIdx.x;                 // 1024 threads, 8 bins each
    int base = seg * BATCH + t * 8;
    int v[8], s = 0;
#pragma unroll
    for (int j = 0; j < 8; j++) { v[j] = g_cnt[base + j]; s += v[j]; }
    __shared__ int sh[1024];
    sh[t] = s;
    __syncthreads();
    for (int off = 1; off < 1024; off <<= 1) {
        int x = (t >= off) ? sh[t - off] : 0;
        __syncthreads();
        sh[t] += x;
        __syncthreads();
    }
    int run = sh[t] - s;
#pragma unroll
    for (int j = 0; j < 8; j++) {
        g_off[base + j] = run;
        g_cnt[base + j] = run;
        run += v[j];
    }
}

__global__ void scatter_kernel(const int* __restrict__ usrc, const int* __restrict__ udst,
                               const float* __restrict__ uw,
                               const int* __restrict__ isrc, const int* __restrict__ idst,
                               const float* __restrict__ iw) {
    int i = blockIdx.x * 256 + threadIdx.x;
    if (i >= SEGS * EDGES) return;
    int seg = i / EDGES, e = i - seg * EDGES;
    int src, dst; float w;
    if (seg < CLASSES) {
        int o = seg * EDGES + e;
        src = usrc[o]; dst = udst[o]; w = uw[o];
    } else {
        int o = (seg - CLASSES) * EDGES + e;
        src = isrc[o]; dst = idst[o]; w = iw[o];
    }
    int pos = atomicAdd(&g_cnt[seg * BATCH + dst], 1);
    g_ssrc[seg * EDGES + pos] = src;
    g_sw  [seg * EDGES + pos] = w;
}

// ---------------- aggregation: float4 lanes, 4 edge slots, 2-deep unroll ----
__global__ void agg_kernel(const float* __restrict__ user_feat,
                           const float* __restrict__ item_feat) {
    int dst = blockIdx.x;
    int seg = blockIdx.y;
    int tid  = threadIdx.x;
    int lane = tid & 63;        // feature quad 0..63
    int slot = tid >> 6;        // edge slot 0..3
    const float4* feat = (const float4*)((seg < CLASSES) ? item_feat : user_feat);
    int start = g_off[seg * BATCH + dst];
    int end   = g_cnt[seg * BATCH + dst];
    const int*   ss = g_ssrc + seg * EDGES;
    const float* sw = g_sw   + seg * EDGES;

    float4 acc = make_float4(0.f, 0.f, 0.f, 0.f);
    int e = start + slot;
    for (; e + 4 < end; e += 8) {
        int   s0 = ss[e];     float w0 = sw[e];
        int   s1 = ss[e + 4]; float w1 = sw[e + 4];
        float4 v0 = feat[(long)s0 * 64 + lane];
        float4 v1 = feat[(long)s1 * 64 + lane];
        acc.x += w0 * v0.x + w1 * v1.x;
        acc.y += w0 * v0.y + w1 * v1.y;
        acc.z += w0 * v0.z + w1 * v1.z;
        acc.w += w0 * v0.w + w1 * v1.w;
    }
    if (e < end) {
        int s = ss[e]; float w = sw[e];
        float4 v = feat[(long)s * 64 + lane];
        acc.x += w * v.x; acc.y += w * v.y; acc.z += w * v.z; acc.w += w * v.w;
    }

    __shared__ float4 red[256];
    red[tid] = acc;
    __syncthreads();
    if (slot == 0) {
        float4 a = red[lane], b = red[64 + lane], c = red[128 + lane], d = red[192 + lane];
        a.x += b.x + c.x + d.x;
        a.y += b.y + c.y + d.y;
        a.z += b.z + c.z + d.z;
        a.w += b.w + c.w + d.w;
        ((float4*)g_agg)[((long)seg * BATCH + dst) * 64 + lane] = a;
    }
}

// ---------------- SGEMM core: 128x64 tile, 8x4 micro, 256 threads -----------
// EPI: 0 = none, 1 = bias+BN+relu, 2 = BN+relu, 3 = add(addend)+relu
template<int EPI>
__device__ __forceinline__ void gemm_body(
    float As[16][132], float Bs[16][68],
    const float* __restrict__ A, const int* __restrict__ gidx, int lda,
    const float* __restrict__ B, int ldb,
    float* __restrict__ C, int ldc, int col0, int K,
    const float* __restrict__ bias,
    const float* __restrict__ bnp, int bn_dim,
    const float* __restrict__ addend, int ldadd)
{
    int m0 = blockIdx.y * 128;
    int n0 = blockIdx.x * 64;
    int tid = threadIdx.x;
    int tx = tid & 15, ty = tid >> 4;
    int arow = tid & 127;           // 0..127
    int ak8  = (tid >> 7) * 8;      // 0 or 8
    int brow = tid >> 4;            // 0..15
    int bn4  = (tid & 15) * 4;

    const float* Arow_ptr;
    {
        int gr = m0 + arow;
        int r  = gidx ? gidx[gr] : gr;
        Arow_ptr = A + (long)r * lda;
    }

    float acc[8][4];
#pragma unroll
    for (int i = 0; i < 8; i++)
#pragma unroll
        for (int j = 0; j < 4; j++) acc[i][j] = 0.f;

    for (int k0 = 0; k0 < K; k0 += 16) {
        float4 a0 = *(const float4*)(Arow_ptr + k0 + ak8);
        float4 a1 = *(const float4*)(Arow_ptr + k0 + ak8 + 4);
        float4 bv = *(const float4*)(B + (long)(k0 + brow) * ldb + n0 + bn4);
        __syncthreads();
        As[ak8 + 0][arow] = a0.x;
        As[ak8 + 1][arow] = a0.y;
        As[ak8 + 2][arow] = a0.z;
        As[ak8 + 3][arow] = a0.w;
        As[ak8 + 4][arow] = a1.x;
        As[ak8 + 5][arow] = a1.y;
        As[ak8 + 6][arow] = a1.z;
        As[ak8 + 7][arow] = a1.w;
        *(float4*)(&Bs[brow][bn4]) = bv;
        __syncthreads();
#pragma unroll
        for (int kk = 0; kk < 16; kk++) {
            float4 pa0 = *(const float4*)(&As[kk][ty * 8]);
            float4 pa1 = *(const float4*)(&As[kk][ty * 8 + 4]);
            float4 pb  = *(const float4*)(&Bs[kk][tx * 4]);
            float ar[8] = {pa0.x, pa0.y, pa0.z, pa0.w, pa1.x, pa1.y, pa1.z, pa1.w};
            float br[4] = {pb.x, pb.y, pb.z, pb.w};
#pragma unroll
            for (int i = 0; i < 8; i++)
#pragma unroll
                for (int j = 0; j < 4; j++)
                    acc[i][j] += ar[i] * br[j];
        }
    }

#pragma unroll
    for (int i = 0; i < 8; i++) {
        int r = m0 + ty * 8 + i;
#pragma unroll
        for (int j = 0; j < 4; j++) {
            int c  = n0 + tx * 4 + j;
            int cg = col0 + c;
            float x = acc[i][j];
            if (EPI == 1) x += bias[c];
            if (EPI == 1 || EPI == 2) {
                float gma  = bnp[cg];
                float beta = bnp[bn_dim + cg];
                float mean = bnp[2 * bn_dim + cg];
                float var  = bnp[3 * bn_dim + cg];
                x = gma * (x - mean) * rsqrtf(var + BN_EPS) + beta;
                x = fmaxf(x, 0.f);
            }
            if (EPI == 3) {
                x += addend[(long)r * ldadd + cg];
                x = fmaxf(x, 0.f);
            }
            C[(long)r * ldc + cg] = x;
        }
    }
}

// dual-z wrapper: blockIdx.z picks parameter set 0 or 1
template<int EPI>
__global__ void sgemm_dual(
    const float* A0, const float* A1, const int* gidx0, const int* gidx1, int lda,
    const float* B0, const float* B1, int ldb,
    float* C0, float* C1, int ldc, int col0, int K,
    const float* bias0, const float* bias1,
    const float* bn0, const float* bn1, int bn_dim,
    const float* add0, const float* add1, int ldadd)
{
    __shared__ float As[16][132];
    __shared__ float Bs[16][68];
    if (blockIdx.z == 0)
        gemm_body<EPI>(As, Bs, A0, gidx0, lda, B0, ldb, C0, ldc, col0, K,
                       bias0, bn0, bn_dim, add0, ldadd);
    else
        gemm_body<EPI>(As, Bs, A1, gidx1, lda, B1, ldb, C1, ldc, col0, K,
                       bias1, bn1, bn_dim, add1, ldadd);
}

// batched class projections: blockIdx.z = seg (0..9)
__global__ void class_proj_kernel(const float* __restrict__ agg,
                                  const float* __restrict__ Wuc, const float* __restrict__ Wic,
                                  const float* __restrict__ bn_hu, const float* __restrict__ bn_hi,
                                  float* __restrict__ hb)
{
    __shared__ float As[16][132];
    __shared__ float Bs[16][68];
    int seg = blockIdx.z;
    int side = seg / CLASSES, c = seg % CLASSES;
    const float* A  = agg + (long)seg * BATCH * N_FEAT;
    const float* B  = (side ? Wic : Wuc) + (long)c * N_FEAT * D_CONV;
    const float* bn = side ? bn_hi : bn_hu;
    float* C = hb + (long)side * BATCH * (CLASSES * D_CONV);
    gemm_body<2>(As, Bs, A, nullptr, N_FEAT, B, D_CONV, C, CLASSES * D_CONV,
                 c * D_CONV, N_FEAT, nullptr, bn, CLASSES * D_CONV, nullptr, 0);
}

// ---------------- bilinear decoder combine ----------------------------------
__global__ void decode_kernel(const float* __restrict__ t0, const float* __restrict__ t1,
                              const float* __restrict__ ve, const float* __restrict__ Wcomb,
                              float* __restrict__ out) {
    int b = blockIdx.x, t = threadIdx.x;  // 256 threads
    float v  = ve[(long)b * D_EMB + t];
    float a0 = t0[(long)b * D_EMB + t] * v;
    float a1 = t1[(long)b * D_EMB + t] * v;
#pragma unroll
    for (int o = 16; o; o >>= 1) {
        a0 += __shfl_down_sync(0xffffffffu, a0, o);
        a1 += __shfl_down_sync(0xffffffffu, a1, o);
    }
    __shared__ float s0[8], s1[8];
    if ((t & 31) == 0) { s0[t >> 5] = a0; s1[t >> 5] = a1; }
    __syncthreads();
    if (t == 0) {
        float d0 = 0.f, d1 = 0.f;
#pragma unroll
        for (int i = 0; i < 8; i++) { d0 += s0[i]; d1 += s1[i]; }
        s0[0] = d0; s1[0] = d1;
    }
    __syncthreads();
    if (t < CLASSES)
        out[(long)b * CLASSES + t] = Wcomb[t * 2] * s0[0] + Wcomb[t * 2 + 1] * s1[0];
}

// ---------------- launch ----------------------------------------------------
extern "C" void kernel_launch(void* const* d_in, const int* in_sizes, int n_in,
                              void* d_out, int out_size) {
    const float* user_feat = (const float*)d_in[0];
    const float* item_feat = (const float*)d_in[1];
    const int*   user_idx  = (const int*)d_in[2];
    const int*   item_idx  = (const int*)d_in[3];
    const int*   u_src     = (const int*)d_in[4];
    const int*   u_dst     = (const int*)d_in[5];
    const float* u_w       = (const float*)d_in[6];
    const int*   i_src     = (const int*)d_in[7];
    const int*   i_dst     = (const int*)d_in[8];
    const float* i_w       = (const float*)d_in[9];
    const float* W_fu      = (const float*)d_in[10];
    const float* b_fu      = (const float*)d_in[11];
    const float* W_fi      = (const float*)d_in[12];
    const float* b_fi      = (const float*)d_in[13];
    const float* W_uc      = (const float*)d_in[14];
    const float* W_ic      = (const float*)d_in[15];
    const float* bn_fu     = (const float*)d_in[16];
    const float* bn_hu     = (const float*)d_in[17];
    const float* bn_fi     = (const float*)d_in[18];
    const float* bn_hi     = (const float*)d_in[19];
    const float* W2_fu     = (const float*)d_in[20];
    const float* W2_hu     = (const float*)d_in[21];
    const float* W2_fi     = (const float*)d_in[22];
    const float* W2_hi     = (const float*)d_in[23];
    const float* Wdec      = (const float*)d_in[24];
    const float* Wcomb     = (const float*)d_in[25];
    float* out = (float*)d_out;

    void* p;
    cudaGetSymbolAddress(&p, g_agg); float* agg  = (float*)p;
    cudaGetSymbolAddress(&p, g_f);   float* fb   = (float*)p;
    cudaGetSymbolAddress(&p, g_h);   float* hb   = (float*)p;
    cudaGetSymbolAddress(&p, g_tmp); float* tmp  = (float*)p;
    cudaGetSymbolAddress(&p, g_emb); float* emb  = (float*)p;
    cudaGetSymbolAddress(&p, g_t);   float* tdec = (float*)p;

    const int HD = CLASSES * D_CONV;  // 640

    // 1) edge counting-sort by dst (per segment)
    zero_cnt_kernel<<<(SEGS * BATCH + 255) / 256, 256>>>();
    int eblocks = (SEGS * EDGES + 255) / 256;
    hist_kernel<<<eblocks, 256>>>(u_dst, i_dst);
    scan_kernel<<<SEGS, 1024>>>();
    scatter_kernel<<<eblocks, 256>>>(u_src, u_dst, u_w, i_src, i_dst, i_w);

    // 2) per-bucket weighted aggregation (no float atomics)
    agg_kernel<<<dim3(BATCH, SEGS), 256>>>(user_feat, item_feat);

    // 3) f projections: gather + GEMM + bias + BN + relu  (dual-z: user/item)
    sgemm_dual<1><<<dim3(4, 64, 2), 256>>>(
        user_feat, item_feat, user_idx, item_idx, N_FEAT,
        W_fu, W_fi, 256,
        fb, fb + (long)BATCH * 256, 256, 0, N_FEAT,
        b_fu, b_fi, bn_fu, bn_fi, 256, nullptr, nullptr, 0);

    // 4) all 10 class projections in one launch
    class_proj_kernel<<<dim3(2, 64, 10), 256>>>(agg, W_uc, W_ic, bn_hu, bn_hi, hb);

    // 5) embeddings: tmp = f @ W2_f ; emb = relu(tmp + h @ W2_h)
    sgemm_dual<0><<<dim3(4, 64, 2), 256>>>(
        fb, fb + (long)BATCH * 256, nullptr, nullptr, 256,
        W2_fu, W2_fi, D_EMB,
        tmp, tmp + (long)BATCH * D_EMB, D_EMB, 0, 256,
        nullptr, nullptr, nullptr, nullptr, 0, nullptr, nullptr, 0);
    sgemm_dual<3><<<dim3(4, 64, 2), 256>>>(
        hb, hb + (long)BATCH * HD, nullptr, nullptr, HD,
        W2_hu, W2_hi, D_EMB,
        emb, emb + (long)BATCH * D_EMB, D_EMB, 0, HD,
        nullptr, nullptr, nullptr, nullptr, 0, tmp, tmp + (long)BATCH * D_EMB, D_EMB);

    // 6) bilinear decoder: t_k = user_emb @ Wdec[k] (dual-z over basis), combine
    float* uemb = emb;
    float* iemb = emb + (long)BATCH * D_EMB;
    sgemm_dual<0><<<dim3(4, 64, 2), 256>>>(
        uemb, uemb, nullptr, nullptr, D_EMB,
        Wdec, Wdec + D_EMB * D_EMB, D_EMB,
        tdec, tdec + (long)BATCH * D_EMB, D_EMB, 0, D_EMB,
        nullptr, nullptr, nullptr, nullptr, 0, nullptr, nullptr, 0);
    decode_kernel<<<BATCH, 256>>>(tdec, tdec + (long)BATCH * D_EMB, iemb, Wcomb, out);
}

// round 3
// speedup vs baseline: 1.6307x; 1.0260x over previous
#include <cuda_runtime.h>
#include <cuda_bf16.h>

#define N_FEAT   256
#define BATCH    8192
#define CLASSES  5
#define EDGES    500000
#define D_CONV   128
#define D_EMB    256
#define SEGS     10
#define BN_EPS   1e-3f

// ---------------- scratch ----------------------------------------------------
__device__ int   g_cnt [SEGS * BATCH];
__device__ int   g_off [SEGS * BATCH];
__device__ int2  g_ep  [SEGS * EDGES];          // packed (src, weight-bits)
__device__ float g_agg [SEGS * BATCH * N_FEAT];
__device__ float g_f   [2 * BATCH * N_FEAT];
__device__ float g_h   [2 * BATCH * CLASSES * D_CONV];
__device__ float g_emb [2 * BATCH * D_EMB];
__device__ float g_t   [2 * BATCH * D_EMB];

// ---------------- counting sort of edges by dst, per segment ----------------
__global__ void zero_cnt_kernel() {
    int i = blockIdx.x * 256 + threadIdx.x;
    if (i < SEGS * BATCH) g_cnt[i] = 0;
}

__global__ void hist_kernel(const int* __restrict__ udst, const int* __restrict__ idst) {
    int i = blockIdx.x * 256 + threadIdx.x;
    if (i >= SEGS * EDGES) return;
    int seg = i / EDGES, e = i - seg * EDGES;
    int dst = (seg < CLASSES) ? udst[seg * EDGES + e] : idst[(seg - CLASSES) * EDGES + e];
    atomicAdd(&g_cnt[seg * BATCH + dst], 1);
}

__global__ void scan_kernel() {
    int seg = blockIdx.x;
    int t = threadIdx.x;                 // 1024 threads, 8 bins each
    int base = seg * BATCH + t * 8;
    int v[8], s = 0;
#pragma unroll
    for (int j = 0; j < 8; j++) { v[j] = g_cnt[base + j]; s += v[j]; }
    __shared__ int sh[1024];
    sh[t] = s;
    __syncthreads();
    for (int off = 1; off < 1024; off <<= 1) {
        int x = (t >= off) ? sh[t - off] : 0;
        __syncthreads();
        sh[t] += x;
        __syncthreads();
    }
    int run = sh[t] - s;
#pragma unroll
    for (int j = 0; j < 8; j++) {
        g_off[base + j] = run;
        g_cnt[base + j] = run;
        run += v[j];
    }
}

__global__ void scatter_kernel(const int* __restrict__ usrc, const int* __restrict__ udst,
                               const float* __restrict__ uw,
                               const int* __restrict__ isrc, const int* __restrict__ idst,
                               const float* __restrict__ iw) {
    int i = blockIdx.x * 256 + threadIdx.x;
    if (i >= SEGS * EDGES) return;
    int seg = i / EDGES, e = i - seg * EDGES;
    int src, dst; float w;
    if (seg < CLASSES) {
        int o = seg * EDGES + e;
        src = usrc[o]; dst = udst[o]; w = uw[o];
    } else {
        int o = (seg - CLASSES) * EDGES + e;
        src = isrc[o]; dst = idst[o]; w = iw[o];
    }
    int pos = atomicAdd(&g_cnt[seg * BATCH + dst], 1);
    g_ep[seg * EDGES + pos] = make_int2(src, __float_as_int(w));
}

// ---------------- aggregation: float4 lanes, 4 edge slots, packed edges -----
__global__ void agg_kernel(const float* __restrict__ user_feat,
                           const float* __restrict__ item_feat) {
    int dst = blockIdx.x;
    int seg = blockIdx.y;
    int tid  = threadIdx.x;
    int lane = tid & 63;        // feature quad 0..63
    int slot = tid >> 6;        // edge slot 0..3
    const float4* feat = (const float4*)((seg < CLASSES) ? item_feat : user_feat);
    int start = g_off[seg * BATCH + dst];
    int end   = g_cnt[seg * BATCH + dst];
    const int2* ep = g_ep + seg * EDGES;

    float4 acc = make_float4(0.f, 0.f, 0.f, 0.f);
    int e = start + slot;
    for (; e + 4 < end; e += 8) {
        int2 p0 = ep[e];
        int2 p1 = ep[e + 4];
        float w0 = __int_as_float(p0.y), w1 = __int_as_float(p1.y);
        float4 v0 = feat[(long)p0.x * 64 + lane];
        float4 v1 = feat[(long)p1.x * 64 + lane];
        acc.x += w0 * v0.x + w1 * v1.x;
        acc.y += w0 * v0.y + w1 * v1.y;
        acc.z += w0 * v0.z + w1 * v1.z;
        acc.w += w0 * v0.w + w1 * v1.w;
    }
    if (e < end) {
        int2 p = ep[e];
        float w = __int_as_float(p.y);
        float4 v = feat[(long)p.x * 64 + lane];
        acc.x += w * v.x; acc.y += w * v.y; acc.z += w * v.z; acc.w += w * v.w;
    }

    __shared__ float4 red[256];
    red[tid] = acc;
    __syncthreads();
    if (slot == 0) {
        float4 a = red[lane], b = red[64 + lane], c = red[128 + lane], d = red[192 + lane];
        a.x += b.x + c.x + d.x;
        a.y += b.y + c.y + d.y;
        a.z += b.z + c.z + d.z;
        a.w += b.w + c.w + d.w;
        ((float4*)g_agg)[((long)seg * BATCH + dst) * 64 + lane] = a;
    }
}

// ---------------- SGEMM: 128x128 tile, 8x8 micro, double-buffered -----------
// EPI: 0 = none, 1 = bias+BN+relu, 2 = BN+relu, 3 = relu
// Split-K inputs: A1/B1 for k < ksplit, A2/B2 after (fused concat GEMM).
template<int EPI>
__device__ __forceinline__ void gemm_core(
    float (&As)[2][8][132], float (&Bs)[2][8][132],
    const float* __restrict__ A1, const float* __restrict__ A2,
    int lda1, int lda2, int ksplit, const int* __restrict__ gidx,
    const float* __restrict__ B1, const float* __restrict__ B2, int ldb,
    float* __restrict__ C, int ldc, int col0, int K,
    const float* __restrict__ bias, const float* __restrict__ bnp, int bn_dim)
{
    const int tid = threadIdx.x;
    const int m0 = blockIdx.y * 128, n0 = blockIdx.x * 128;
    const int tx = tid & 15, ty = tid >> 4;
    const int arow = tid & 127, ak = (tid >> 7) * 4;
    const int brow = tid >> 5, bcol = (tid & 31) * 4;

    const float *Ap1, *Ap2 = nullptr;
    {
        int gr = m0 + arow;
        int r = gidx ? gidx[gr] : gr;
        Ap1 = A1 + (long)r * lda1 + ak;
        if (A2) Ap2 = A2 + (long)r * lda2 + ak;
    }
    const float* Bb1 = B1 + (long)brow * ldb + n0 + bcol;
    const float* Bb2 = B2 ? (B2 + (long)brow * ldb + n0 + bcol) : nullptr;

    float acc[8][8];
#pragma unroll
    for (int i = 0; i < 8; i++)
#pragma unroll
        for (int j = 0; j < 8; j++) acc[i][j] = 0.f;

    float4 aR = *(const float4*)(Ap1);
    float4 bR = *(const float4*)(Bb1);
    As[0][ak + 0][arow] = aR.x;
    As[0][ak + 1][arow] = aR.y;
    As[0][ak + 2][arow] = aR.z;
    As[0][ak + 3][arow] = aR.w;
    *(float4*)&Bs[0][brow][bcol] = bR;
    __syncthreads();

    const int nc = K / 8;
    for (int c = 0; c < nc; c++) {
        int cur = c & 1;
        if (c + 1 < nc) {
            int k0 = (c + 1) * 8;
            if (k0 < ksplit) {
                aR = *(const float4*)(Ap1 + k0);
                bR = *(const float4*)(Bb1 + (long)k0 * ldb);
            } else {
                aR = *(const float4*)(Ap2 + (k0 - ksplit));
                bR = *(const float4*)(Bb2 + (long)(k0 - ksplit) * ldb);
            }
        }
#pragma unroll
        for (int kk = 0; kk < 8; kk++) {
            float4 a0 = *(const float4*)&As[cur][kk][ty * 4];
            float4 a1 = *(const float4*)&As[cur][kk][64 + ty * 4];
            float4 b0 = *(const float4*)&Bs[cur][kk][tx * 4];
            float4 b1 = *(const float4*)&Bs[cur][kk][64 + tx * 4];
            float av[8] = {a0.x, a0.y, a0.z, a0.w, a1.x, a1.y, a1.z, a1.w};
            float bv[8] = {b0.x, b0.y, b0.z, b0.w, b1.x, b1.y, b1.z, b1.w};
#pragma unroll
            for (int i = 0; i < 8; i++)
#pragma unroll
                for (int j = 0; j < 8; j++)
                    acc[i][j] += av[i] * bv[j];
        }
        if (c + 1 < nc) {
            int nxt = cur ^ 1;
            As[nxt][ak + 0][arow] = aR.x;
            As[nxt][ak + 1][arow] = aR.y;
            As[nxt][ak + 2][arow] = aR.z;
            As[nxt][ak + 3][arow] = aR.w;
            *(float4*)&Bs[nxt][brow][bcol] = bR;
            __syncthreads();
        }
    }

#pragma unroll
    for (int i = 0; i < 8; i++) {
        int r = m0 + ((i < 4) ? (ty * 4 + i) : (64 + ty * 4 + i - 4));
#pragma unroll
        for (int jj = 0; jj < 2; jj++) {
            int cbase = n0 + jj * 64 + tx * 4;
            float4 v;
            float* vp = &v.x;
#pragma unroll
            for (int j = 0; j < 4; j++) {
                float x = acc[i][jj * 4 + j];
                int cg = col0 + cbase + j;
                if (EPI == 1) x += bias[cbase + j];
                if (EPI == 1 || EPI == 2) {
                    float gm = bnp[cg];
                    float be = bnp[bn_dim + cg];
                    float mn = bnp[2 * bn_dim + cg];
                    float vr = bnp[3 * bn_dim + cg];
                    x = gm * (x - mn) * rsqrtf(vr + BN_EPS) + be;
                    x = fmaxf(x, 0.f);
                }
                if (EPI == 3) x = fmaxf(x, 0.f);
                vp[j] = x;
            }
            *(float4*)(C + (long)r * ldc + col0 + cbase) = v;
        }
    }
}

template<int EPI>
__global__ void __launch_bounds__(256, 2) gemm_dual(
    const float* A1a, const float* A1b, const float* A2a, const float* A2b,
    int lda1, int lda2, int ksplit,
    const int* gx0, const int* gx1,
    const float* B1a, const float* B1b, const float* B2a, const float* B2b, int ldb,
    float* C0, float* C1, int ldc, int K,
    const float* bias0, const float* bias1,
    const float* bn0, const float* bn1, int bn_dim)
{
    __shared__ float As[2][8][132];
    __shared__ float Bs[2][8][132];
    if (blockIdx.z == 0)
        gemm_core<EPI>(As, Bs, A1a, A2a, lda1, lda2, ksplit, gx0, B1a, B2a, ldb,
                       C0, ldc, 0, K, bias0, bn0, bn_dim);
    else
        gemm_core<EPI>(As, Bs, A1b, A2b, lda1, lda2, ksplit, gx1, B1b, B2b, ldb,
                       C1, ldc, 0, K, bias1, bn1, bn_dim);
}

// all 10 class projections in one launch (blockIdx.z = seg)
__global__ void __launch_bounds__(256, 2) class_proj_kernel(
    const float* __restrict__ agg,
    const float* __restrict__ Wuc, const float* __restrict__ Wic,
    const float* __restrict__ bn_hu, const float* __restrict__ bn_hi,
    float* __restrict__ hb)
{
    __shared__ float As[2][8][132];
    __shared__ float Bs[2][8][132];
    int seg = blockIdx.z;
    int side = seg / CLASSES, c = seg % CLASSES;
    const float* A  = agg + (long)seg * BATCH * N_FEAT;
    const float* B  = (side ? Wic : Wuc) + (long)c * N_FEAT * D_CONV;
    const float* bn = side ? bn_hi : bn_hu;
    float* C = hb + (long)side * BATCH * (CLASSES * D_CONV);
    gemm_core<2>(As, Bs, A, nullptr, N_FEAT, 0, N_FEAT, nullptr, B, nullptr, D_CONV,
                 C, CLASSES * D_CONV, c * D_CONV, N_FEAT, nullptr, bn, CLASSES * D_CONV);
}

// ---------------- bilinear decoder combine ----------------------------------
__global__ void decode_kernel(const float* __restrict__ t0, const float* __restrict__ t1,
                              const float* __restrict__ ve, const float* __restrict__ Wcomb,
                              float* __restrict__ out) {
    int b = blockIdx.x, t = threadIdx.x;  // 256 threads
    float v  = ve[(long)b * D_EMB + t];
    float a0 = t0[(long)b * D_EMB + t] * v;
    float a1 = t1[(long)b * D_EMB + t] * v;
#pragma unroll
    for (int o = 16; o; o >>= 1) {
        a0 += __shfl_down_sync(0xffffffffu, a0, o);
        a1 += __shfl_down_sync(0xffffffffu, a1, o);
    }
    __shared__ float s0[8], s1[8];
    if ((t & 31) == 0) { s0[t >> 5] = a0; s1[t >> 5] = a1; }
    __syncthreads();
    if (t == 0) {
        float d0 = 0.f, d1 = 0.f;
#pragma unroll
        for (int i = 0; i < 8; i++) { d0 += s0[i]; d1 += s1[i]; }
        s0[0] = d0; s1[0] = d1;
    }
    __syncthreads();
    if (t < CLASSES)
        out[(long)b * CLASSES + t] = Wcomb[t * 2] * s0[0] + Wcomb[t * 2 + 1] * s1[0];
}

// ---------------- launch ----------------------------------------------------
extern "C" void kernel_launch(void* const* d_in, const int* in_sizes, int n_in,
                              void* d_out, int out_size) {
    const float* user_feat = (const float*)d_in[0];
    const float* item_feat = (const float*)d_in[1];
    const int*   user_idx  = (const int*)d_in[2];
    const int*   item_idx  = (const int*)d_in[3];
    const int*   u_src     = (const int*)d_in[4];
    const int*   u_dst     = (const int*)d_in[5];
    const float* u_w       = (const float*)d_in[6];
    const int*   i_src     = (const int*)d_in[7];
    const int*   i_dst     = (const int*)d_in[8];
    const float* i_w       = (const float*)d_in[9];
    const float* W_fu      = (const float*)d_in[10];
    const float* b_fu      = (const float*)d_in[11];
    const float* W_fi      = (const float*)d_in[12];
    const float* b_fi      = (const float*)d_in[13];
    const float* W_uc      = (const float*)d_in[14];
    const float* W_ic      = (const float*)d_in[15];
    const float* bn_fu     = (const float*)d_in[16];
    const float* bn_hu     = (const float*)d_in[17];
    const float* bn_fi     = (const float*)d_in[18];
    const float* bn_hi     = (const float*)d_in[19];
    const float* W2_fu     = (const float*)d_in[20];
    const float* W2_hu     = (const float*)d_in[21];
    const float* W2_fi     = (const float*)d_in[22];
    const float* W2_hi     = (const float*)d_in[23];
    const float* Wdec      = (const float*)d_in[24];
    const float* Wcomb     = (const float*)d_in[25];
    float* out = (float*)d_out;

    void* p;
    cudaGetSymbolAddress(&p, g_agg); float* agg  = (float*)p;
    cudaGetSymbolAddress(&p, g_f);   float* fb   = (float*)p;
    cudaGetSymbolAddress(&p, g_h);   float* hb   = (float*)p;
    cudaGetSymbolAddress(&p, g_emb); float* emb  = (float*)p;
    cudaGetSymbolAddress(&p, g_t);   float* tdec = (float*)p;

    const int HD = CLASSES * D_CONV;  // 640

    // 1) edge counting-sort by dst (per segment)
    zero_cnt_kernel<<<(SEGS * BATCH + 255) / 256, 256>>>();
    int eblocks = (SEGS * EDGES + 255) / 256;
    hist_kernel<<<eblocks, 256>>>(u_dst, i_dst);
    scan_kernel<<<SEGS, 1024>>>();
    scatter_kernel<<<eblocks, 256>>>(u_src, u_dst, u_w, i_src, i_dst, i_w);

    // 2) per-bucket weighted aggregation (no float atomics)
    agg_kernel<<<dim3(BATCH, SEGS), 256>>>(user_feat, item_feat);

    // 3) f projections: gather + GEMM + bias + BN + relu (dual-z: user/item)
    gemm_dual<1><<<dim3(2, 64, 2), 256>>>(
        user_feat, item_feat, nullptr, nullptr, N_FEAT, 0, 1 << 30,
        user_idx, item_idx,
        W_fu, W_fi, nullptr, nullptr, 256,
        fb, fb + (long)BATCH * 256, 256, N_FEAT,
        b_fu, b_fi, bn_fu, bn_fi, 256);

    // 4) all 10 class projections in one launch
    class_proj_kernel<<<dim3(1, 64, 10), 256>>>(agg, W_uc, W_ic, bn_hu, bn_hi, hb);

    // 5) fused embeddings: emb = relu([f|h] @ [W2_f; W2_h]), K = 256+640
    gemm_dual<3><<<dim3(2, 64, 2), 256>>>(
        fb, fb + (long)BATCH * 256, hb, hb + (long)BATCH * HD,
        256, HD, 256,
        nullptr, nullptr,
        W2_fu, W2_fi, W2_hu, W2_hi, D_EMB,
        emb, emb + (long)BATCH * D_EMB, D_EMB, 256 + HD,
        nullptr, nullptr, nullptr, nullptr, 0);

    // 6) bilinear decoder: t_k = user_emb @ Wdec[k] (dual-z over basis), combine
    float* uemb = emb;
    float* iemb = emb + (long)BATCH * D_EMB;
    gemm_dual<0><<<dim3(2, 64, 2), 256>>>(
        uemb, uemb, nullptr, nullptr, D_EMB, 0, 1 << 30,
        nullptr, nullptr,
        Wdec, Wdec + D_EMB * D_EMB, nullptr, nullptr, D_EMB,
        tdec, tdec + (long)BATCH * D_EMB, D_EMB, D_EMB,
        nullptr, nullptr, nullptr, nullptr, 0);
    decode_kernel<<<BATCH, 256>>>(tdec, tdec + (long)BATCH * D_EMB, iemb, Wcomb, out);
}

// round 8
// speedup vs baseline: 1.8309x; 1.1228x over previous
#include <cuda_runtime.h>
#include <cuda_bf16.h>
#include <mma.h>
#include <cstdint>

using namespace nvcuda;

#define N_FEAT   256
#define BATCH    8192
#define CLASSES  5
#define EDGES    500000
#define D_CONV   128
#define D_EMB    256
#define SEGS     10
#define BN_EPS   1e-3f

#define ASTRIDE 20    // A smem row stride (floats), mult of 4
#define BSTRIDE 132   // B smem row stride (floats), mult of 4
#define CSTRIDE 20    // staging row stride

// ---------------- scratch ----------------------------------------------------
__device__ int   g_cnt [SEGS * BATCH];
__device__ int   g_off [SEGS * BATCH];
__device__ int2  g_ep  [SEGS * EDGES];
__device__ float g_agg [SEGS * BATCH * N_FEAT];
__device__ float g_f   [2 * BATCH * N_FEAT];
__device__ float g_h   [2 * BATCH * CLASSES * D_CONV];
__device__ float g_emb [2 * BATCH * D_EMB];
__device__ float g_t   [2 * BATCH * D_EMB];

// ---------------- counting sort of edges by dst, per segment ----------------
__global__ void zero_cnt_kernel() {
    int i = blockIdx.x * 256 + threadIdx.x;
    if (i < SEGS * BATCH) g_cnt[i] = 0;
}

__global__ void hist_kernel(const int* __restrict__ udst, const int* __restrict__ idst) {
    int i = blockIdx.x * 256 + threadIdx.x;
    if (i >= SEGS * EDGES) return;
    int seg = i / EDGES, e = i - seg * EDGES;
    int dst = (seg < CLASSES) ? udst[seg * EDGES + e] : idst[(seg - CLASSES) * EDGES + e];
    atomicAdd(&g_cnt[seg * BATCH + dst], 1);
}

__global__ void scan_kernel() {
    int seg = blockIdx.x;
    int t = threadIdx.x;
    int base = seg * BATCH + t * 8;
    int v[8], s = 0;
#pragma unroll
    for (int j = 0; j < 8; j++) { v[j] = g_cnt[base + j]; s += v[j]; }
    __shared__ int sh[1024];
    sh[t] = s;
    __syncthreads();
    for (int off = 1; off < 1024; off <<= 1) {
        int x = (t >= off) ? sh[t - off] : 0;
        __syncthreads();
        sh[t] += x;
        __syncthreads();
    }
    int run = sh[t] - s;
#pragma unroll
    for (int j = 0; j < 8; j++) {
        g_off[base + j] = run;
        g_cnt[base + j] = run;
        run += v[j];
    }
}

__global__ void scatter_kernel(const int* __restrict__ usrc, const int* __restrict__ udst,
                               const float* __restrict__ uw,
                               const int* __restrict__ isrc, const int* __restrict__ idst,
                               const float* __restrict__ iw) {
    int i = blockIdx.x * 256 + threadIdx.x;
    if (i >= SEGS * EDGES) return;
    int seg = i / EDGES, e = i - seg * EDGES;
    int src, dst; float w;
    if (seg < CLASSES) {
        int o = seg * EDGES + e;
        src = usrc[o]; dst = udst[o]; w = uw[o];
    } else {
        int o = (seg - CLASSES) * EDGES + e;
        src = isrc[o]; dst = idst[o]; w = iw[o];
    }
    int pos = atomicAdd(&g_cnt[seg * BATCH + dst], 1);
    g_ep[seg * EDGES + pos] = make_int2(src, __float_as_int(w));
}

// ---------------- aggregation ------------------------------------------------
__global__ void agg_kernel(const float* __restrict__ user_feat,
                           const float* __restrict__ item_feat) {
    int dst = blockIdx.x;
    int seg = blockIdx.y;
    int tid  = threadIdx.x;
    int lane = tid & 63;
    int slot = tid >> 6;
    const float4* feat = (const float4*)((seg < CLASSES) ? item_feat : user_feat);
    int start = g_off[seg * BATCH + dst];
    int end   = g_cnt[seg * BATCH + dst];
    const int2* ep = g_ep + seg * EDGES;

    float4 acc = make_float4(0.f, 0.f, 0.f, 0.f);
    int e = start + slot;
    for (; e + 4 < end; e += 8) {
        int2 p0 = ep[e];
        int2 p1 = ep[e + 4];
        float w0 = __int_as_float(p0.y), w1 = __int_as_float(p1.y);
        float4 v0 = feat[(long)p0.x * 64 + lane];
        float4 v1 = feat[(long)p1.x * 64 + lane];
        acc.x += w0 * v0.x + w1 * v1.x;
        acc.y += w0 * v0.y + w1 * v1.y;
        acc.z += w0 * v0.z + w1 * v1.z;
        acc.w += w0 * v0.w + w1 * v1.w;
    }
    if (e < end) {
        int2 p = ep[e];
        float w = __int_as_float(p.y);
        float4 v = feat[(long)p.x * 64 + lane];
        acc.x += w * v.x; acc.y += w * v.y; acc.z += w * v.z; acc.w += w * v.w;
    }

    __shared__ float4 red[256];
    red[tid] = acc;
    __syncthreads();
    if (slot == 0) {
        float4 a = red[lane], b = red[64 + lane], c = red[128 + lane], d = red[192 + lane];
        a.x += b.x + c.x + d.x;
        a.y += b.y + c.y + d.y;
        a.z += b.z + c.z + d.z;
        a.w += b.w + c.w + d.w;
        ((float4*)g_agg)[((long)seg * BATCH + dst) * 64 + lane] = a;
    }
}

// ---------------- tf32 WMMA GEMM ---------------------------------------------
// 128x128 tile, 8 warps (2m x 4n), warp = 64x32 via wmma m16n16k8 (4x2 tiles).
// EPI: 0 = none, 1 = bias+BN+relu, 2 = BN+relu, 3 = relu

__device__ __forceinline__ uint32_t f2tf(float f) {
    uint32_t r;
    asm("cvt.rna.tf32.f32 %0, %1;" : "=r"(r) : "f"(f));
    return r;
}

template<int EPI>
__device__ __forceinline__ void gemm_core(
    uint32_t (&As)[2][128][ASTRIDE], uint32_t (&Bs)[2][16][BSTRIDE],
    float (&stage)[8][16][CSTRIDE],
    const float* __restrict__ A1, const float* __restrict__ A2,
    int lda1, int lda2, int ksplit, const int* __restrict__ gidx,
    const float* __restrict__ B1, const float* __restrict__ B2, int ldb,
    float* __restrict__ C, int ldc, int col0, int K,
    const float* __restrict__ bias, const float* __restrict__ bnp, int bn_dim)
{
    const int tid = threadIdx.x;
    const int m0 = blockIdx.y * 128, n0 = blockIdx.x * 128;
    const int warp = tid >> 5, lane = tid & 31;
    const int wm0 = (warp & 1) * 64, wn0 = (warp >> 1) * 32;

    const int arow = tid & 127, ahalf = (tid >> 7) * 8;
    const int brow = tid >> 4, bcol = (tid & 15) * 8;

    const float *Ap1, *Ap2 = nullptr;
    {
        int r = gidx ? gidx[m0 + arow] : (m0 + arow);
        Ap1 = A1 + (long)r * lda1;
        if (A2) Ap2 = A2 + (long)r * lda2;
    }
    const float* Bp1 = B1 + n0 + bcol;
    const float* Bp2 = B2 ? (B2 + n0 + bcol) : nullptr;

    wmma::fragment<wmma::accumulator, 16, 16, 8, float> facc[4][2];
#pragma unroll
    for (int i = 0; i < 4; i++)
#pragma unroll
        for (int j = 0; j < 2; j++) wmma::fill_fragment(facc[i][j], 0.f);

    float a_st[8], b_st[8];

    auto load_chunk = [&](int k0) {
        const float *ap, *bp;
        if (k0 < ksplit) {
            ap = Ap1 + k0 + ahalf;
            bp = Bp1 + (long)(k0 + brow) * ldb;
        } else {
            ap = Ap2 + (k0 - ksplit) + ahalf;
            bp = Bp2 + (long)(k0 - ksplit + brow) * ldb;
        }
        float4 x = *(const float4*)ap;
        float4 y = *(const float4*)(ap + 4);
        a_st[0] = x.x; a_st[1] = x.y; a_st[2] = x.z; a_st[3] = x.w;
        a_st[4] = y.x; a_st[5] = y.y; a_st[6] = y.z; a_st[7] = y.w;
        float4 u = *(const float4*)bp;
        float4 v = *(const float4*)(bp + 4);
        b_st[0] = u.x; b_st[1] = u.y; b_st[2] = u.z; b_st[3] = u.w;
        b_st[4] = v.x; b_st[5] = v.y; b_st[6] = v.z; b_st[7] = v.w;
    };

    auto store_chunk = [&](int buf) {
        // A row-major: As[buf][row][k], 16B-aligned vector stores
        uint4 q0 = make_uint4(f2tf(a_st[0]), f2tf(a_st[1]), f2tf(a_st[2]), f2tf(a_st[3]));
        uint4 q1 = make_uint4(f2tf(a_st[4]), f2tf(a_st[5]), f2tf(a_st[6]), f2tf(a_st[7]));
        *(uint4*)&As[buf][arow][ahalf]     = q0;
        *(uint4*)&As[buf][arow][ahalf + 4] = q1;
        uint4 p0 = make_uint4(f2tf(b_st[0]), f2tf(b_st[1]), f2tf(b_st[2]), f2tf(b_st[3]));
        uint4 p1 = make_uint4(f2tf(b_st[4]), f2tf(b_st[5]), f2tf(b_st[6]), f2tf(b_st[7]));
        *(uint4*)&Bs[buf][brow][bcol]     = p0;
        *(uint4*)&Bs[buf][brow][bcol + 4] = p1;
    };

    const int nc = K / 16;
    load_chunk(0);
    store_chunk(0);
    __syncthreads();

    for (int ch = 0; ch < nc; ch++) {
        int cur = ch & 1;
        if (ch + 1 < nc) load_chunk((ch + 1) * 16);
#pragma unroll
        for (int s = 0; s < 2; s++) {
            const int kb = s * 8;
            wmma::fragment<wmma::matrix_b, 16, 16, 8, wmma::precision::tf32, wmma::row_major> fb0, fb1;
            wmma::load_matrix_sync(fb0, (const float*)&Bs[cur][kb][wn0],      BSTRIDE);
            wmma::load_matrix_sync(fb1, (const float*)&Bs[cur][kb][wn0 + 16], BSTRIDE);
#pragma unroll
            for (int ma = 0; ma < 4; ma++) {
                wmma::fragment<wmma::matrix_a, 16, 16, 8, wmma::precision::tf32, wmma::row_major> fa;
                wmma::load_matrix_sync(fa, (const float*)&As[cur][wm0 + ma * 16][kb], ASTRIDE);
                wmma::mma_sync(facc[ma][0], fa, fb0, facc[ma][0]);
                wmma::mma_sync(facc[ma][1], fa, fb1, facc[ma][1]);
            }
        }
        if (ch + 1 < nc) {
            store_chunk(cur ^ 1);
            __syncthreads();
        }
    }

    // epilogue: stage each 16x16 tile through smem, apply post-ops, store
    __syncthreads();
    const int srow = lane >> 1;            // 0..15
    const int scol = (lane & 1) * 8;       // 0 or 8
#pragma unroll
    for (int ma = 0; ma < 4; ma++) {
#pragma unroll
        for (int na = 0; na < 2; na++) {
            wmma::store_matrix_sync(&stage[warp][0][0], facc[ma][na], CSTRIDE, wmma::mem_row_major);
            __syncwarp();
            int r  = m0 + wm0 + ma * 16 + srow;
            int cb = n0 + wn0 + na * 16 + scol;   // global C column (pre-col0)
            float x[8];
#pragma unroll
            for (int j = 0; j < 8; j++) {
                float v = stage[warp][srow][scol + j];
                int cgl = cb + j;
                int cg  = col0 + cgl;
                if (EPI == 1) v += bias[cgl];
                if (EPI == 1 || EPI == 2) {
                    float gm = bnp[cg];
                    float be = bnp[bn_dim + cg];
                    float mn = bnp[2 * bn_dim + cg];
                    float vr = bnp[3 * bn_dim + cg];
                    v = gm * (v - mn) * rsqrtf(vr + BN_EPS) + be;
                    v = fmaxf(v, 0.f);
                }
                if (EPI == 3) v = fmaxf(v, 0.f);
                x[j] = v;
            }
            float* cp = C + (long)r * ldc + col0 + cb;
            *(float4*)(cp)     = make_float4(x[0], x[1], x[2], x[3]);
            *(float4*)(cp + 4) = make_float4(x[4], x[5], x[6], x[7]);
            __syncwarp();
        }
    }
}

template<int EPI>
__global__ void __launch_bounds__(256, 2) gemm_dual(
    const float* A1a, const float* A1b, const float* A2a, const float* A2b,
    int lda1, int lda2, int ksplit,
    const int* gx0, const int* gx1,
    const float* B1a, const float* B1b, const float* B2a, const float* B2b, int ldb,
    float* C0, float* C1, int ldc, int K,
    const float* bias0, const float* bias1,
    const float* bn0, const float* bn1, int bn_dim)
{
    __shared__ uint32_t As[2][128][ASTRIDE];
    __shared__ uint32_t Bs[2][16][BSTRIDE];
    __shared__ float    St[8][16][CSTRIDE];
    if (blockIdx.z == 0)
        gemm_core<EPI>(As, Bs, St, A1a, A2a, lda1, lda2, ksplit, gx0, B1a, B2a, ldb,
                       C0, ldc, 0, K, bias0, bn0, bn_dim);
    else
        gemm_core<EPI>(As, Bs, St, A1b, A2b, lda1, lda2, ksplit, gx1, B1b, B2b, ldb,
                       C1, ldc, 0, K, bias1, bn1, bn_dim);
}

__global__ void __launch_bounds__(256, 2) class_proj_kernel(
    const float* __restrict__ agg,
    const float* __restrict__ Wuc, const float* __restrict__ Wic,
    const float* __restrict__ bn_hu, const float* __restrict__ bn_hi,
    float* __restrict__ hb)
{
    __shared__ uint32_t As[2][128][ASTRIDE];
    __shared__ uint32_t Bs[2][16][BSTRIDE];
    __shared__ float    St[8][16][CSTRIDE];
    int seg = blockIdx.z;
    int side = seg / CLASSES, c = seg % CLASSES;
    const float* A  = agg + (long)seg * BATCH * N_FEAT;
    const float* B  = (side ? Wic : Wuc) + (long)c * N_FEAT * D_CONV;
    const float* bn = side ? bn_hi : bn_hu;
    float* C = hb + (long)side * BATCH * (CLASSES * D_CONV);
    gemm_core<2>(As, Bs, St, A, nullptr, N_FEAT, 0, 1 << 30, nullptr, B, nullptr, D_CONV,
                 C, CLASSES * D_CONV, c * D_CONV, N_FEAT, nullptr, bn, CLASSES * D_CONV);
}

// ---------------- bilinear decoder combine ----------------------------------
__global__ void decode_kernel(const float* __restrict__ t0, const float* __restrict__ t1,
                              const float* __restrict__ ve, const float* __restrict__ Wcomb,
                              float* __restrict__ out) {
    int b = blockIdx.x, t = threadIdx.x;
    float v  = ve[(long)b * D_EMB + t];
    float a0 = t0[(long)b * D_EMB + t] * v;
    float a1 = t1[(long)b * D_EMB + t] * v;
#pragma unroll
    for (int o = 16; o; o >>= 1) {
        a0 += __shfl_down_sync(0xffffffffu, a0, o);
        a1 += __shfl_down_sync(0xffffffffu, a1, o);
    }
    __shared__ float s0[8], s1[8];
    if ((t & 31) == 0) { s0[t >> 5] = a0; s1[t >> 5] = a1; }
    __syncthreads();
    if (t == 0) {
        float d0 = 0.f, d1 = 0.f;
#pragma unroll
        for (int i = 0; i < 8; i++) { d0 += s0[i]; d1 += s1[i]; }
        s0[0] = d0; s1[0] = d1;
    }
    __syncthreads();
    if (t < CLASSES)
        out[(long)b * CLASSES + t] = Wcomb[t * 2] * s0[0] + Wcomb[t * 2 + 1] * s1[0];
}

// ---------------- launch ----------------------------------------------------
extern "C" void kernel_launch(void* const* d_in, const int* in_sizes, int n_in,
                              void* d_out, int out_size) {
    const float* user_feat = (const float*)d_in[0];
    const float* item_feat = (const float*)d_in[1];
    const int*   user_idx  = (const int*)d_in[2];
    const int*   item_idx  = (const int*)d_in[3];
    const int*   u_src     = (const int*)d_in[4];
    const int*   u_dst     = (const int*)d_in[5];
    const float* u_w       = (const float*)d_in[6];
    const int*   i_src     = (const int*)d_in[7];
    const int*   i_dst     = (const int*)d_in[8];
    const float* i_w       = (const float*)d_in[9];
    const float* W_fu      = (const float*)d_in[10];
    const float* b_fu      = (const float*)d_in[11];
    const float* W_fi      = (const float*)d_in[12];
    const float* b_fi      = (const float*)d_in[13];
    const float* W_uc      = (const float*)d_in[14];
    const float* W_ic      = (const float*)d_in[15];
    const float* bn_fu     = (const float*)d_in[16];
    const float* bn_hu     = (const float*)d_in[17];
    const float* bn_fi     = (const float*)d_in[18];
    const float* bn_hi     = (const float*)d_in[19];
    const float* W2_fu     = (const float*)d_in[20];
    const float* W2_hu     = (const float*)d_in[21];
    const float* W2_fi     = (const float*)d_in[22];
    const float* W2_hi     = (const float*)d_in[23];
    const float* Wdec      = (const float*)d_in[24];
    const float* Wcomb     = (const float*)d_in[25];
    float* out = (float*)d_out;

    void* p;
    cudaGetSymbolAddress(&p, g_agg); float* agg  = (float*)p;
    cudaGetSymbolAddress(&p, g_f);   float* fb   = (float*)p;
    cudaGetSymbolAddress(&p, g_h);   float* hb   = (float*)p;
    cudaGetSymbolAddress(&p, g_emb); float* emb  = (float*)p;
    cudaGetSymbolAddress(&p, g_t);   float* tdec = (float*)p;

    const int HD = CLASSES * D_CONV;  // 640

    // 1) edge counting-sort by dst (per segment)
    zero_cnt_kernel<<<(SEGS * BATCH + 255) / 256, 256>>>();
    int eblocks = (SEGS * EDGES + 255) / 256;
    hist_kernel<<<eblocks, 256>>>(u_dst, i_dst);
    scan_kernel<<<SEGS, 1024>>>();
    scatter_kernel<<<eblocks, 256>>>(u_src, u_dst, u_w, i_src, i_dst, i_w);

    // 2) per-bucket weighted aggregation
    agg_kernel<<<dim3(BATCH, SEGS), 256>>>(user_feat, item_feat);

    // 3) f projections: gather + GEMM + bias + BN + relu (dual-z: user/item)
    gemm_dual<1><<<dim3(2, 64, 2), 256>>>(
        user_feat, item_feat, nullptr, nullptr, N_FEAT, 0, 1 << 30,
        user_idx, item_idx,
        W_fu, W_fi, nullptr, nullptr, 256,
        fb, fb + (long)BATCH * 256, 256, N_FEAT,
        b_fu, b_fi, bn_fu, bn_fi, 256);

    // 4) all 10 class projections in one launch
    class_proj_kernel<<<dim3(1, 64, 10), 256>>>(agg, W_uc, W_ic, bn_hu, bn_hi, hb);

    // 5) fused embeddings: emb = relu([f|h] @ [W2_f; W2_h]), K = 256+640
    gemm_dual<3><<<dim3(2, 64, 2), 256>>>(
        fb, fb + (long)BATCH * 256, hb, hb + (long)BATCH * HD,
        256, HD, 256,
        nullptr, nullptr,
        W2_fu, W2_fi, W2_hu, W2_hi, D_EMB,
        emb, emb + (long)BATCH * D_EMB, D_EMB, 256 + HD,
        nullptr, nullptr, nullptr, nullptr, 0);

    // 6) bilinear decoder
    float* uemb = emb;
    float* iemb = emb + (long)BATCH * D_EMB;
    gemm_dual<0><<<dim3(2, 64, 2), 256>>>(
        uemb, uemb, nullptr, nullptr, D_EMB, 0, 1 << 30,
        nullptr, nullptr,
        Wdec, Wdec + D_EMB * D_EMB, nullptr, nullptr, D_EMB,
        tdec, tdec + (long)BATCH * D_EMB, D_EMB, D_EMB,
        nullptr, nullptr, nullptr, nullptr, 0);
    decode_kernel<<<BATCH, 256>>>(tdec, tdec + (long)BATCH * D_EMB, iemb, Wcomb, out);
}

// round 9
// speedup vs baseline: 2.2359x; 1.2212x over previous
#include <cuda_runtime.h>
#include <cuda_fp16.h>
#include <cuda_bf16.h>
#include <mma.h>
#include <cstdint>

using namespace nvcuda;

#define N_USERS  100000
#define N_ITEMS  100000
#define N_FEAT   256
#define BATCH    8192
#define CLASSES  5
#define EDGES    500000
#define D_CONV   128
#define D_EMB    256
#define SEGS     10
#define BN_EPS   1e-3f

#define ASTRIDE 20    // A smem row stride (floats), mult of 4
#define BSTRIDE 132   // B smem row stride (floats), mult of 4
#define CSTRIDE 20    // staging row stride

// ---------------- scratch ----------------------------------------------------
__device__ int    g_cnt [SEGS * BATCH];
__device__ int    g_off [SEGS * BATCH];
__device__ int2   g_ep  [SEGS * EDGES];
__device__ __half g_u16 [(long)N_USERS * N_FEAT];
__device__ __half g_i16 [(long)N_ITEMS * N_FEAT];
__device__ float  g_agg [SEGS * BATCH * N_FEAT];
__device__ float  g_f   [2 * BATCH * N_FEAT];
__device__ float  g_h   [2 * BATCH * CLASSES * D_CONV];
__device__ float  g_emb [2 * BATCH * D_EMB];
__device__ float  g_t   [2 * BATCH * D_EMB];

// ---------------- fp16 conversion of feature tables -------------------------
__global__ void tofp16_kernel(const float* __restrict__ uf, const float* __restrict__ itf) {
    long i = (long)blockIdx.x * 256 + threadIdx.x;           // float4 index
    const long Q = (long)N_USERS * N_FEAT / 4;               // per table
    if (i < Q) {
        float4 v = ((const float4*)uf)[i];
        __half2* o = (__half2*)g_u16;
        o[i * 2]     = __floats2half2_rn(v.x, v.y);
        o[i * 2 + 1] = __floats2half2_rn(v.z, v.w);
    } else if (i < 2 * Q) {
        long j = i - Q;
        float4 v = ((const float4*)itf)[j];
        __half2* o = (__half2*)g_i16;
        o[j * 2]     = __floats2half2_rn(v.x, v.y);
        o[j * 2 + 1] = __floats2half2_rn(v.z, v.w);
    }
}

// ---------------- counting sort of edges by dst, per segment ----------------
__global__ void zero_cnt_kernel() {
    int i = blockIdx.x * 256 + threadIdx.x;
    if (i < SEGS * BATCH) g_cnt[i] = 0;
}

#define EQUARTER (SEGS * EDGES / 4)   // 1,250,000

__global__ void hist_kernel(const int* __restrict__ udst, const int* __restrict__ idst) {
    int i = blockIdx.x * 256 + threadIdx.x;
    if (i >= EQUARTER) return;
#pragma unroll
    for (int j = 0; j < 4; j++) {
        int idx = i + j * EQUARTER;
        int seg = idx / EDGES, e = idx - seg * EDGES;
        int dst = (seg < CLASSES) ? udst[seg * EDGES + e] : idst[(seg - CLASSES) * EDGES + e];
        atomicAdd(&g_cnt[seg * BATCH + dst], 1);
    }
}

__global__ void scan_kernel() {
    int seg = blockIdx.x;
    int t = threadIdx.x;
    int base = seg * BATCH + t * 8;
    int v[8], s = 0;
#pragma unroll
    for (int j = 0; j < 8; j++) { v[j] = g_cnt[base + j]; s += v[j]; }
    __shared__ int sh[1024];
    sh[t] = s;
    __syncthreads();
    for (int off = 1; off < 1024; off <<= 1) {
        int x = (t >= off) ? sh[t - off] : 0;
        __syncthreads();
        sh[t] += x;
        __syncthreads();
    }
    int run = sh[t] - s;
#pragma unroll
    for (int j = 0; j < 8; j++) {
        g_off[base + j] = run;
        g_cnt[base + j] = run;
        run += v[j];
    }
}

__global__ void scatter_kernel(const int* __restrict__ usrc, const int* __restrict__ udst,
                               const float* __restrict__ uw,
                               const int* __restrict__ isrc, const int* __restrict__ idst,
                               const float* __restrict__ iw) {
    int i = blockIdx.x * 256 + threadIdx.x;
    if (i >= EQUARTER) return;
#pragma unroll
    for (int j = 0; j < 4; j++) {
        int idx = i + j * EQUARTER;
        int seg = idx / EDGES, e = idx - seg * EDGES;
        int src, dst; float w;
        if (seg < CLASSES) {
            int o = seg * EDGES + e;
            src = usrc[o]; dst = udst[o]; w = uw[o];
        } else {
            int o = (seg - CLASSES) * EDGES + e;
            src = isrc[o]; dst = idst[o]; w = iw[o];
        }
        int pos = atomicAdd(&g_cnt[seg * BATCH + dst], 1);
        g_ep[seg * EDGES + pos] = make_int2(src, __float_as_int(w));
    }
}

// ---------------- aggregation: fp16 feature gather --------------------------
// 32 lanes x 8 features (uint4 = 8 halves), 8 edge slots per block
__global__ void agg_kernel() {
    int dst = blockIdx.x;
    int seg = blockIdx.y;
    int tid  = threadIdx.x;
    int lane = tid & 31;        // feature octet 0..31
    int slot = tid >> 5;        // edge slot 0..7
    const uint4* feat = (const uint4*)((seg < CLASSES) ? g_i16 : g_u16);
    int start = g_off[seg * BATCH + dst];
    int end   = g_cnt[seg * BATCH + dst];
    const int2* ep = g_ep + seg * EDGES;

    float acc[8];
#pragma unroll
    for (int j = 0; j < 8; j++) acc[j] = 0.f;

    for (int e = start + slot; e < end; e += 8) {
        int2 p = ep[e];
        float w = __int_as_float(p.y);
        uint4 v = feat[(long)p.x * 32 + lane];
        const __half2* h = (const __half2*)&v;
#pragma unroll
        for (int q = 0; q < 4; q++) {
            float2 f = __half22float2(h[q]);
            acc[q * 2]     += w * f.x;
            acc[q * 2 + 1] += w * f.y;
        }
    }

    __shared__ float red[256][8];
#pragma unroll
    for (int j = 0; j < 8; j++) red[tid][j] = acc[j];
    __syncthreads();
    if (slot == 0) {
        float s[8];
#pragma unroll
        for (int j = 0; j < 8; j++) s[j] = red[lane][j];
#pragma unroll
        for (int k = 1; k < 8; k++)
#pragma unroll
            for (int j = 0; j < 8; j++) s[j] += red[k * 32 + lane][j];
        float4* outp = (float4*)(g_agg + ((long)seg * BATCH + dst) * N_FEAT + lane * 8);
        outp[0] = make_float4(s[0], s[1], s[2], s[3]);
        outp[1] = make_float4(s[4], s[5], s[6], s[7]);
    }
}

// ---------------- tf32 WMMA GEMM ---------------------------------------------
// 128x128 tile, 8 warps (2m x 4n), warp = 64x32 via wmma m16n16k8 (4x2 tiles).
// EPI: 0 = none, 1 = bias+BN+relu, 2 = BN+relu, 3 = relu

__device__ __forceinline__ uint32_t f2tf(float f) {
    uint32_t r;
    asm("cvt.rna.tf32.f32 %0, %1;" : "=r"(r) : "f"(f));
    return r;
}

template<int EPI>
__device__ __forceinline__ void gemm_core(
    uint32_t (&As)[2][128][ASTRIDE], uint32_t (&Bs)[2][16][BSTRIDE],
    float (&stage)[8][16][CSTRIDE],
    const float* __restrict__ A1, const float* __restrict__ A2,
    int lda1, int lda2, int ksplit, const int* __restrict__ gidx,
    const float* __restrict__ B1, const float* __restrict__ B2, int ldb,
    float* __restrict__ C, int ldc, int col0, int K,
    const float* __restrict__ bias, const float* __restrict__ bnp, int bn_dim)
{
    const int tid = threadIdx.x;
    const int m0 = blockIdx.y * 128, n0 = blockIdx.x * 128;
    const int warp = tid >> 5, lane = tid & 31;
    const int wm0 = (warp & 1) * 64, wn0 = (warp >> 1) * 32;

    const int arow = tid & 127, ahalf = (tid >> 7) * 8;
    const int brow = tid >> 4, bcol = (tid & 15) * 8;

    const float *Ap1, *Ap2 = nullptr;
    {
        int r = gidx ? gidx[m0 + arow] : (m0 + arow);
        Ap1 = A1 + (long)r * lda1;
        if (A2) Ap2 = A2 + (long)r * lda2;
    }
    const float* Bp1 = B1 + n0 + bcol;
    const float* Bp2 = B2 ? (B2 + n0 + bcol) : nullptr;

    wmma::fragment<wmma::accumulator, 16, 16, 8, float> facc[4][2];
#pragma unroll
    for (int i = 0; i < 4; i++)
#pragma unroll
        for (int j = 0; j < 2; j++) wmma::fill_fragment(facc[i][j], 0.f);

    float a_st[8], b_st[8];

    auto load_chunk = [&](int k0) {
        const float *ap, *bp;
        if (k0 < ksplit) {
            ap = Ap1 + k0 + ahalf;
            bp = Bp1 + (long)(k0 + brow) * ldb;
        } else {
            ap = Ap2 + (k0 - ksplit) + ahalf;
            bp = Bp2 + (long)(k0 - ksplit + brow) * ldb;
        }
        float4 x = *(const float4*)ap;
        float4 y = *(const float4*)(ap + 4);
        a_st[0] = x.x; a_st[1] = x.y; a_st[2] = x.z; a_st[3] = x.w;
        a_st[4] = y.x; a_st[5] = y.y; a_st[6] = y.z; a_st[7] = y.w;
        float4 u = *(const float4*)bp;
        float4 v = *(const float4*)(bp + 4);
        b_st[0] = u.x; b_st[1] = u.y; b_st[2] = u.z; b_st[3] = u.w;
        b_st[4] = v.x; b_st[5] = v.y; b_st[6] = v.z; b_st[7] = v.w;
    };

    auto store_chunk = [&](int buf) {
        uint4 q0 = make_uint4(f2tf(a_st[0]), f2tf(a_st[1]), f2tf(a_st[2]), f2tf(a_st[3]));
        uint4 q1 = make_uint4(f2tf(a_st[4]), f2tf(a_st[5]), f2tf(a_st[6]), f2tf(a_st[7]));
        *(uint4*)&As[buf][arow][ahalf]     = q0;
        *(uint4*)&As[buf][arow][ahalf + 4] = q1;
        uint4 p0 = make_uint4(f2tf(b_st[0]), f2tf(b_st[1]), f2tf(b_st[2]), f2tf(b_st[3]));
        uint4 p1 = make_uint4(f2tf(b_st[4]), f2tf(b_st[5]), f2tf(b_st[6]), f2tf(b_st[7]));
        *(uint4*)&Bs[buf][brow][bcol]     = p0;
        *(uint4*)&Bs[buf][brow][bcol + 4] = p1;
    };

    const int nc = K / 16;
    load_chunk(0);
    store_chunk(0);
    __syncthreads();

    for (int ch = 0; ch < nc; ch++) {
        int cur = ch & 1;
        if (ch + 1 < nc) load_chunk((ch + 1) * 16);
#pragma unroll
        for (int s = 0; s < 2; s++) {
            const int kb = s * 8;
            wmma::fragment<wmma::matrix_b, 16, 16, 8, wmma::precision::tf32, wmma::row_major> fb0, fb1;
            wmma::load_matrix_sync(fb0, (const float*)&Bs[cur][kb][wn0],      BSTRIDE);
            wmma::load_matrix_sync(fb1, (const float*)&Bs[cur][kb][wn0 + 16], BSTRIDE);
#pragma unroll
            for (int ma = 0; ma < 4; ma++) {
                wmma::fragment<wmma::matrix_a, 16, 16, 8, wmma::precision::tf32, wmma::row_major> fa;
                wmma::load_matrix_sync(fa, (const float*)&As[cur][wm0 + ma * 16][kb], ASTRIDE);
                wmma::mma_sync(facc[ma][0], fa, fb0, facc[ma][0]);
                wmma::mma_sync(facc[ma][1], fa, fb1, facc[ma][1]);
            }
        }
        if (ch + 1 < nc) {
            store_chunk(cur ^ 1);
            __syncthreads();
        }
    }

    // epilogue: stage each 16x16 tile through smem, apply post-ops, store
    __syncthreads();
    const int srow = lane >> 1;
    const int scol = (lane & 1) * 8;
#pragma unroll
    for (int ma = 0; ma < 4; ma++) {
#pragma unroll
        for (int na = 0; na < 2; na++) {
            wmma::store_matrix_sync(&stage[warp][0][0], facc[ma][na], CSTRIDE, wmma::mem_row_major);
            __syncwarp();
            int r  = m0 + wm0 + ma * 16 + srow;
            int cb = n0 + wn0 + na * 16 + scol;
            float x[8];
#pragma unroll
            for (int j = 0; j < 8; j++) {
                float v = stage[warp][srow][scol + j];
                int cgl = cb + j;
                int cg  = col0 + cgl;
                if (EPI == 1) v += bias[cgl];
                if (EPI == 1 || EPI == 2) {
                    float gm = bnp[cg];
                    float be = bnp[bn_dim + cg];
                    float mn = bnp[2 * bn_dim + cg];
                    float vr = bnp[3 * bn_dim + cg];
                    v = gm * (v - mn) * rsqrtf(vr + BN_EPS) + be;
                    v = fmaxf(v, 0.f);
                }
                if (EPI == 3) v = fmaxf(v, 0.f);
                x[j] = v;
            }
            float* cp = C + (long)r * ldc + col0 + cb;
            *(float4*)(cp)     = make_float4(x[0], x[1], x[2], x[3]);
            *(float4*)(cp + 4) = make_float4(x[4], x[5], x[6], x[7]);
            __syncwarp();
        }
    }
}

template<int EPI>
__global__ void __launch_bounds__(256, 2) gemm_dual(
    const float* A1a, const float* A1b, const float* A2a, const float* A2b,
    int lda1, int lda2, int ksplit,
    const int* gx0, const int* gx1,
    const float* B1a, const float* B1b, const float* B2a, const float* B2b, int ldb,
    float* C0, float* C1, int ldc, int K,
    const float* bias0, const float* bias1,
    const float* bn0, const float* bn1, int bn_dim)
{
    __shared__ uint32_t As[2][128][ASTRIDE];
    __shared__ uint32_t Bs[2][16][BSTRIDE];
    __shared__ float    St[8][16][CSTRIDE];
    if (blockIdx.z == 0)
        gemm_core<EPI>(As, Bs, St, A1a, A2a, lda1, lda2, ksplit, gx0, B1a, B2a, ldb,
                       C0, ldc, 0, K, bias0, bn0, bn_dim);
    else
        gemm_core<EPI>(As, Bs, St, A1b, A2b, lda1, lda2, ksplit, gx1, B1b, B2b, ldb,
                       C1, ldc, 0, K, bias1, bn1, bn_dim);
}

__global__ void __launch_bounds__(256, 2) class_proj_kernel(
    const float* __restrict__ agg,
    const float* __restrict__ Wuc, const float* __restrict__ Wic,
    const float* __restrict__ bn_hu, const float* __restrict__ bn_hi,
    float* __restrict__ hb)
{
    __shared__ uint32_t As[2][128][ASTRIDE];
    __shared__ uint32_t Bs[2][16][BSTRIDE];
    __shared__ float    St[8][16][CSTRIDE];
    int seg = blockIdx.z;
    int side = seg / CLASSES, c = seg % CLASSES;
    const float* A  = agg + (long)seg * BATCH * N_FEAT;
    const float* B  = (side ? Wic : Wuc) + (long)c * N_FEAT * D_CONV;
    const float* bn = side ? bn_hi : bn_hu;
    float* C = hb + (long)side * BATCH * (CLASSES * D_CONV);
    gemm_core<2>(As, Bs, St, A, nullptr, N_FEAT, 0, 1 << 30, nullptr, B, nullptr, D_CONV,
                 C, CLASSES * D_CONV, c * D_CONV, N_FEAT, nullptr, bn, CLASSES * D_CONV);
}

// ---------------- bilinear decoder combine ----------------------------------
__global__ void decode_kernel(const float* __restrict__ t0, const float* __restrict__ t1,
                              const float* __restrict__ ve, const float* __restrict__ Wcomb,
                              float* __restrict__ out) {
    int b = blockIdx.x, t = threadIdx.x;
    float v  = ve[(long)b * D_EMB + t];
    float a0 = t0[(long)b * D_EMB + t] * v;
    float a1 = t1[(long)b * D_EMB + t] * v;
#pragma unroll
    for (int o = 16; o; o >>= 1) {
        a0 += __shfl_down_sync(0xffffffffu, a0, o);
        a1 += __shfl_down_sync(0xffffffffu, a1, o);
    }
    __shared__ float s0[8], s1[8];
    if ((t & 31) == 0) { s0[t >> 5] = a0; s1[t >> 5] = a1; }
    __syncthreads();
    if (t == 0) {
        float d0 = 0.f, d1 = 0.f;
#pragma unroll
        for (int i = 0; i < 8; i++) { d0 += s0[i]; d1 += s1[i]; }
        s0[0] = d0; s1[0] = d1;
    }
    __syncthreads();
    if (t < CLASSES)
        out[(long)b * CLASSES + t] = Wcomb[t * 2] * s0[0] + Wcomb[t * 2 + 1] * s1[0];
}

// ---------------- launch ----------------------------------------------------
extern "C" void kernel_launch(void* const* d_in, const int* in_sizes, int n_in,
                              void* d_out, int out_size) {
    const float* user_feat = (const float*)d_in[0];
    const float* item_feat = (const float*)d_in[1];
    const int*   user_idx  = (const int*)d_in[2];
    const int*   item_idx  = (const int*)d_in[3];
    const int*   u_src     = (const int*)d_in[4];
    const int*   u_dst     = (const int*)d_in[5];
    const float* u_w       = (const float*)d_in[6];
    const int*   i_src     = (const int*)d_in[7];
    const int*   i_dst     = (const int*)d_in[8];
    const float* i_w       = (const float*)d_in[9];
    const float* W_fu      = (const float*)d_in[10];
    const float* b_fu      = (const float*)d_in[11];
    const float* W_fi      = (const float*)d_in[12];
    const float* b_fi      = (const float*)d_in[13];
    const float* W_uc      = (const float*)d_in[14];
    const float* W_ic      = (const float*)d_in[15];
    const float* bn_fu     = (const float*)d_in[16];
    const float* bn_hu     = (const float*)d_in[17];
    const float* bn_fi     = (const float*)d_in[18];
    const float* bn_hi     = (const float*)d_in[19];
    const float* W2_fu     = (const float*)d_in[20];
    const float* W2_hu     = (const float*)d_in[21];
    const float* W2_fi     = (const float*)d_in[22];
    const float* W2_hi     = (const float*)d_in[23];
    const float* Wdec      = (const float*)d_in[24];
    const float* Wcomb     = (const float*)d_in[25];
    float* out = (float*)d_out;

    void* p;
    cudaGetSymbolAddress(&p, g_agg); float* agg  = (float*)p;
    cudaGetSymbolAddress(&p, g_f);   float* fb   = (float*)p;
    cudaGetSymbolAddress(&p, g_h);   float* hb   = (float*)p;
    cudaGetSymbolAddress(&p, g_emb); float* emb  = (float*)p;
    cudaGetSymbolAddress(&p, g_t);   float* tdec = (float*)p;

    const int HD = CLASSES * D_CONV;  // 640

    // 0) fp16 feature tables (independent of sort chain)
    {
        long q = 2L * N_USERS * N_FEAT / 4;
        tofp16_kernel<<<(int)((q + 255) / 256), 256>>>(user_feat, item_feat);
    }

    // 1) edge counting-sort by dst (per segment), 4-edge ILP
    zero_cnt_kernel<<<(SEGS * BATCH + 255) / 256, 256>>>();
    int qblocks = (EQUARTER + 255) / 256;
    hist_kernel<<<qblocks, 256>>>(u_dst, i_dst);
    scan_kernel<<<SEGS, 1024>>>();
    scatter_kernel<<<qblocks, 256>>>(u_src, u_dst, u_w, i_src, i_dst, i_w);

    // 2) per-bucket weighted aggregation (fp16 gathers, fp32 accumulate)
    agg_kernel<<<dim3(BATCH, SEGS), 256>>>();

    // 3) f projections: gather + GEMM + bias + BN + relu (dual-z: user/item)
    gemm_dual<1><<<dim3(2, 64, 2), 256>>>(
        user_feat, item_feat, nullptr, nullptr, N_FEAT, 0, 1 << 30,
        user_idx, item_idx,
        W_fu, W_fi, nullptr, nullptr, 256,
        fb, fb + (long)BATCH * 256, 256, N_FEAT,
        b_fu, b_fi, bn_fu, bn_fi, 256);

    // 4) all 10 class projections in one launch
    class_proj_kernel<<<dim3(1, 64, 10), 256>>>(agg, W_uc, W_ic, bn_hu, bn_hi, hb);

    // 5) fused embeddings: emb = relu([f|h] @ [W2_f; W2_h]), K = 256+640
    gemm_dual<3><<<dim3(2, 64, 2), 256>>>(
        fb, fb + (long)BATCH * 256, hb, hb + (long)BATCH * HD,
        256, HD, 256,
        nullptr, nullptr,
        W2_fu, W2_fi, W2_hu, W2_hi, D_EMB,
        emb, emb + (long)BATCH * D_EMB, D_EMB, 256 + HD,
        nullptr, nullptr, nullptr, nullptr, 0);

    // 6) bilinear decoder
    float* uemb = emb;
    float* iemb = emb + (long)BATCH * D_EMB;
    gemm_dual<0><<<dim3(2, 64, 2), 256>>>(
        uemb, uemb, nullptr, nullptr, D_EMB, 0, 1 << 30,
        nullptr, nullptr,
        Wdec, Wdec + D_EMB * D_EMB, nullptr, nullptr, D_EMB,
        tdec, tdec + (long)BATCH * D_EMB, D_EMB, D_EMB,
        nullptr, nullptr, nullptr, nullptr, 0);
    decode_kernel<<<BATCH, 256>>>(tdec, tdec + (long)BATCH * D_EMB, iemb, Wcomb, out);
}

// round 12
// speedup vs baseline: 2.2649x; 1.0130x over previous
#include <cuda_runtime.h>
#include <cuda_fp16.h>
#include <cuda_bf16.h>
#include <mma.h>
#include <cstdint>

using namespace nvcuda;

#define N_USERS  100000
#define N_ITEMS  100000
#define N_FEAT   256
#define BATCH    8192
#define CLASSES  5
#define EDGES    500000
#define D_CONV   128
#define D_EMB    256
#define SEGS     10
#define BN_EPS   1e-3f

#define ASTRIDE 12    // A smem row stride (floats): 8 k + 4 pad
#define CSTRIDE 20    // staging row stride

// ---------------- scratch ----------------------------------------------------
__device__ int    g_cnt [SEGS * BATCH];
__device__ int    g_off [SEGS * BATCH];
__device__ int2   g_ep  [SEGS * EDGES];
__device__ __half g_u16 [(long)N_USERS * N_FEAT];
__device__ __half g_i16 [(long)N_ITEMS * N_FEAT];
__device__ float  g_agg [SEGS * BATCH * N_FEAT];
__device__ float  g_f   [2 * BATCH * N_FEAT];
__device__ float  g_h   [2 * BATCH * CLASSES * D_CONV];
__device__ float  g_emb [2 * BATCH * D_EMB];
__device__ float  g_t   [2 * BATCH * D_EMB];

// ---------------- fp16 conversion of feature tables -------------------------
__global__ void tofp16_kernel(const float* __restrict__ uf, const float* __restrict__ itf) {
    long i = (long)blockIdx.x * 256 + threadIdx.x;
    const long Q = (long)N_USERS * N_FEAT / 4;
    if (i < Q) {
        float4 v = ((const float4*)uf)[i];
        __half2* o = (__half2*)g_u16;
        o[i * 2]     = __floats2half2_rn(v.x, v.y);
        o[i * 2 + 1] = __floats2half2_rn(v.z, v.w);
    } else if (i < 2 * Q) {
        long j = i - Q;
        float4 v = ((const float4*)itf)[j];
        __half2* o = (__half2*)g_i16;
        o[j * 2]     = __floats2half2_rn(v.x, v.y);
        o[j * 2 + 1] = __floats2half2_rn(v.z, v.w);
    }
}

// ---------------- counting sort of edges by dst, per segment ----------------
__global__ void zero_cnt_kernel() {
    int i = blockIdx.x * 256 + threadIdx.x;
    if (i < SEGS * BATCH) g_cnt[i] = 0;
}

#define EQUARTER (SEGS * EDGES / 4)

__global__ void hist_kernel(const int* __restrict__ udst, const int* __restrict__ idst) {
    int i = blockIdx.x * 256 + threadIdx.x;
    if (i >= EQUARTER) return;
#pragma unroll
    for (int j = 0; j < 4; j++) {
        int idx = i + j * EQUARTER;
        int seg = idx / EDGES, e = idx - seg * EDGES;
        int dst = (seg < CLASSES) ? udst[seg * EDGES + e] : idst[(seg - CLASSES) * EDGES + e];
        atomicAdd(&g_cnt[seg * BATCH + dst], 1);
    }
}

__global__ void scan_kernel() {
    int seg = blockIdx.x;
    int t = threadIdx.x;
    int base = seg * BATCH + t * 8;
    int v[8], s = 0;
#pragma unroll
    for (int j = 0; j < 8; j++) { v[j] = g_cnt[base + j]; s += v[j]; }
    __shared__ int sh[1024];
    sh[t] = s;
    __syncthreads();
    for (int off = 1; off < 1024; off <<= 1) {
        int x = (t >= off) ? sh[t - off] : 0;
        __syncthreads();
        sh[t] += x;
        __syncthreads();
    }
    int run = sh[t] - s;
#pragma unroll
    for (int j = 0; j < 8; j++) {
        g_off[base + j] = run;
        g_cnt[base + j] = run;
        run += v[j];
    }
}

__global__ void scatter_kernel(const int* __restrict__ usrc, const int* __restrict__ udst,
                               const float* __restrict__ uw,
                               const int* __restrict__ isrc, const int* __restrict__ idst,
                               const float* __restrict__ iw) {
    int i = blockIdx.x * 256 + threadIdx.x;
    if (i >= EQUARTER) return;
#pragma unroll
    for (int j = 0; j < 4; j++) {
        int idx = i + j * EQUARTER;
        int seg = idx / EDGES, e = idx - seg * EDGES;
        int src, dst; float w;
        if (seg < CLASSES) {
            int o = seg * EDGES + e;
            src = usrc[o]; dst = udst[o]; w = uw[o];
        } else {
            int o = (seg - CLASSES) * EDGES + e;
            src = isrc[o]; dst = idst[o]; w = iw[o];
        }
        int pos = atomicAdd(&g_cnt[seg * BATCH + dst], 1);
        g_ep[seg * EDGES + pos] = make_int2(src, __float_as_int(w));
    }
}

// ---------------- aggregation: fp16 feature gather --------------------------
__global__ void agg_kernel() {
    int dst = blockIdx.x;
    int seg = blockIdx.y;
    int tid  = threadIdx.x;
    int lane = tid & 31;
    int slot = tid >> 5;
    const uint4* feat = (const uint4*)((seg < CLASSES) ? g_i16 : g_u16);
    int start = g_off[seg * BATCH + dst];
    int end   = g_cnt[seg * BATCH + dst];
    const int2* ep = g_ep + seg * EDGES;

    float acc[8];
#pragma unroll
    for (int j = 0; j < 8; j++) acc[j] = 0.f;

    for (int e = start + slot; e < end; e += 8) {
        int2 p = ep[e];
        float w = __int_as_float(p.y);
        uint4 v = feat[(long)p.x * 32 + lane];
        const __half2* h = (const __half2*)&v;
#pragma unroll
        for (int q = 0; q < 4; q++) {
            float2 f = __half22float2(h[q]);
            acc[q * 2]     += w * f.x;
            acc[q * 2 + 1] += w * f.y;
        }
    }

    __shared__ float red[256][8];
#pragma unroll
    for (int j = 0; j < 8; j++) red[tid][j] = acc[j];
    __syncthreads();
    if (slot == 0) {
        float s[8];
#pragma unroll
        for (int j = 0; j < 8; j++) s[j] = red[lane][j];
#pragma unroll
        for (int k = 1; k < 8; k++)
#pragma unroll
            for (int j = 0; j < 8; j++) s[j] += red[k * 32 + lane][j];
        float4* outp = (float4*)(g_agg + ((long)seg * BATCH + dst) * N_FEAT + lane * 8);
        outp[0] = make_float4(s[0], s[1], s[2], s[3]);
        outp[1] = make_float4(s[4], s[5], s[6], s[7]);
    }
}

// ---------------- tf32 WMMA GEMM, 64x64 warp tiles ---------------------------
// NW = n-warp count: block 128 x (64*NW), 64*NW threads (2*NW warps).
// warp (wm, wn) = ((warp&1)*64, (warp>>1)*64); each warp 4x4 wmma tiles.
// EPI: 0 = none, 1 = bias+BN+relu, 2 = BN+relu, 3 = relu

__device__ __forceinline__ uint32_t f2tf(float f) {
    uint32_t r;
    asm("cvt.rna.tf32.f32 %0, %1;" : "=r"(r) : "f"(f));
    return r;
}

template<int NW, int EPI>
__device__ __forceinline__ void gemm_core(
    uint32_t (&As)[2][128][ASTRIDE], uint32_t (&Bs)[2][8][64 * NW + 8],
    float (&stage)[2 * NW][16][CSTRIDE],
    const float* __restrict__ A1, const float* __restrict__ A2,
    int lda1, int lda2, int ksplit, const int* __restrict__ gidx,
    const float* __restrict__ B1, const float* __restrict__ B2, int ldb,
    float* __restrict__ C, int ldc, int col0, int K,
    const float* __restrict__ bias, const float* __restrict__ bnp, int bn_dim)
{
    constexpr int T = 64 * NW;          // threads
    constexpr int BST = 64 * NW + 8;    // B smem stride
    const int tid = threadIdx.x;
    const int m0 = blockIdx.y * 128, n0 = blockIdx.x * (64 * NW);
    const int warp = tid >> 5, lane = tid & 31;
    const int wm0 = (warp & 1) * 64, wn0 = (warp >> 1) * 64;

    const int arow = (T == 256) ? (tid & 127) : tid;
    const int ak   = (T == 256) ? ((tid >> 7) * 4) : 0;
    const int brow = (T == 256) ? (tid >> 5) : (tid >> 4);
    const int bcol = (T == 256) ? ((tid & 31) * 8) : ((tid & 15) * 8);

    const float *Ap1, *Ap2 = nullptr;
    {
        int r = gidx ? gidx[m0 + arow] : (m0 + arow);
        Ap1 = A1 + (long)r * lda1;
        if (A2) Ap2 = A2 + (long)r * lda2;
    }
    const float* Bp1 = B1 + n0 + bcol;
    const float* Bp2 = B2 ? (B2 + n0 + bcol) : nullptr;

    wmma::fragment<wmma::accumulator, 16, 16, 8, float> facc[4][4];
#pragma unroll
    for (int i = 0; i < 4; i++)
#pragma unroll
        for (int j = 0; j < 4; j++) wmma::fill_fragment(facc[i][j], 0.f);

    float a_st[(T == 256) ? 4 : 8], b_st[8];

    auto load_chunk = [&](int k0) {
        const float *ap, *bp;
        if (k0 < ksplit) {
            ap = Ap1 + k0 + ak;
            bp = Bp1 + (long)(k0 + brow) * ldb;
        } else {
            ap = Ap2 + (k0 - ksplit) + ak;
            bp = Bp2 + (long)(k0 - ksplit + brow) * ldb;
        }
        float4 x = *(const float4*)ap;
        a_st[0] = x.x; a_st[1] = x.y; a_st[2] = x.z; a_st[3] = x.w;
        if (T == 128) {
            float4 y = *(const float4*)(ap + 4);
            a_st[4] = y.x; a_st[5] = y.y; a_st[6] = y.z; a_st[7] = y.w;
        }
        float4 u = *(const float4*)bp;
        float4 v = *(const float4*)(bp + 4);
        b_st[0] = u.x; b_st[1] = u.y; b_st[2] = u.z; b_st[3] = u.w;
        b_st[4] = v.x; b_st[5] = v.y; b_st[6] = v.z; b_st[7] = v.w;
    };

    auto store_chunk = [&](int buf) {
        uint4 q0 = make_uint4(f2tf(a_st[0]), f2tf(a_st[1]), f2tf(a_st[2]), f2tf(a_st[3]));
        *(uint4*)&As[buf][arow][ak] = q0;
        if (T == 128) {
            uint4 q1 = make_uint4(f2tf(a_st[4]), f2tf(a_st[5]), f2tf(a_st[6]), f2tf(a_st[7]));
            *(uint4*)&As[buf][arow][4] = q1;
        }
        uint4 p0 = make_uint4(f2tf(b_st[0]), f2tf(b_st[1]), f2tf(b_st[2]), f2tf(b_st[3]));
        uint4 p1 = make_uint4(f2tf(b_st[4]), f2tf(b_st[5]), f2tf(b_st[6]), f2tf(b_st[7]));
        *(uint4*)&Bs[buf][brow][bcol]     = p0;
        *(uint4*)&Bs[buf][brow][bcol + 4] = p1;
    };

    const int nc = K / 8;
    load_chunk(0);
    store_chunk(0);
    __syncthreads();

    for (int ch = 0; ch < nc; ch++) {
        int cur = ch & 1;
        if (ch + 1 < nc) load_chunk((ch + 1) * 8);
        wmma::fragment<wmma::matrix_b, 16, 16, 8, wmma::precision::tf32, wmma::row_major> fb[4];
#pragma unroll
        for (int na = 0; na < 4; na++)
            wmma::load_matrix_sync(fb[na], (const float*)&Bs[cur][0][wn0 + na * 16], BST);
#pragma unroll
        for (int ma = 0; ma < 4; ma++) {
            wmma::fragment<wmma::matrix_a, 16, 16, 8, wmma::precision::tf32, wmma::row_major> fa;
            wmma::load_matrix_sync(fa, (const float*)&As[cur][wm0 + ma * 16][0], ASTRIDE);
#pragma unroll
            for (int na = 0; na < 4; na++)
                wmma::mma_sync(facc[ma][na], fa, fb[na], facc[ma][na]);
        }
        if (ch + 1 < nc) {
            store_chunk(cur ^ 1);
            __syncthreads();
        }
    }

    // epilogue: stage each 16x16 tile through smem, apply post-ops, store
    __syncthreads();
    const int srow = lane >> 1;
    const int scol = (lane & 1) * 8;
#pragma unroll
    for (int ma = 0; ma < 4; ma++) {
#pragma unroll
        for (int na = 0; na < 4; na++) {
            wmma::store_matrix_sync(&stage[warp][0][0], facc[ma][na], CSTRIDE, wmma::mem_row_major);
            __syncwarp();
            int r  = m0 + wm0 + ma * 16 + srow;
            int cb = n0 + wn0 + na * 16 + scol;
            float x[8];
#pragma unroll
            for (int j = 0; j < 8; j++) {
                float v = stage[warp][srow][scol + j];
                int cgl = cb + j;
                int cg  = col0 + cgl;
                if (EPI == 1) v += bias[cgl];
                if (EPI == 1 || EPI == 2) {
                    float gm = bnp[cg];
                    float be = bnp[bn_dim + cg];
                    float mn = bnp[2 * bn_dim + cg];
                    float vr = bnp[3 * bn_dim + cg];
                    v = gm * (v - mn) * rsqrtf(vr + BN_EPS) + be;
                    v = fmaxf(v, 0.f);
                }
                if (EPI == 3) v = fmaxf(v, 0.f);
                x[j] = v;
            }
            float* cp = C + (long)r * ldc + col0 + cb;
            *(float4*)(cp)     = make_float4(x[0], x[1], x[2], x[3]);
            *(float4*)(cp + 4) = make_float4(x[4], x[5], x[6], x[7]);
            __syncwarp();
        }
    }
}

// wide kernel: N-tile 256, 256 threads, dual-z parameter sets
template<int EPI>
__global__ void __launch_bounds__(256, 1) gemm_dual(
    const float* A1a, const float* A1b, const float* A2a, const float* A2b,
    int lda1, int lda2, int ksplit,
    const int* gx0, const int* gx1,
    const float* B1a, const float* B1b, const float* B2a, const float* B2b, int ldb,
    float* C0, float* C1, int ldc, int K,
    const float* bias0, const float* bias1,
    const float* bn0, const float* bn1, int bn_dim)
{
    __shared__ uint32_t As[2][128][ASTRIDE];
    __shared__ uint32_t Bs[2][8][264];
    __shared__ float    St[8][16][CSTRIDE];
    if (blockIdx.z == 0)
        gemm_core<4, EPI>(As, Bs, St, A1a, A2a, lda1, lda2, ksplit, gx0, B1a, B2a, ldb,
                          C0, ldc, 0, K, bias0, bn0, bn_dim);
    else
        gemm_core<4, EPI>(As, Bs, St, A1b, A2b, lda1, lda2, ksplit, gx1, B1b, B2b, ldb,
                          C1, ldc, 0, K, bias1, bn1, bn_dim);
}

// narrow kernel: N-tile 128, 128 threads, blockIdx.z = seg (class projections)
__global__ void __launch_bounds__(128, 1) class_proj_kernel(
    const float* __restrict__ agg,
    const float* __restrict__ Wuc, const float* __restrict__ Wic,
    const float* __restrict__ bn_hu, const float* __restrict__ bn_hi,
    float* __restrict__ hb)
{
    __shared__ uint32_t As[2][128][ASTRIDE];
    __shared__ uint32_t Bs[2][8][136];
    __shared__ float    St[4][16][CSTRIDE];
    int seg = blockIdx.z;
    int side = seg / CLASSES, c = seg % CLASSES;
    const float* A  = agg + (long)seg * BATCH * N_FEAT;
    const float* B  = (side ? Wic : Wuc) + (long)c * N_FEAT * D_CONV;
    const float* bn = side ? bn_hi : bn_hu;
    float* C = hb + (long)side * BATCH * (CLASSES * D_CONV);
    gemm_core<2, 2>(As, Bs, St, A, nullptr, N_FEAT, 0, 1 << 30, nullptr, B, nullptr, D_CONV,
                    C, CLASSES * D_CONV, c * D_CONV, N_FEAT, nullptr, bn, CLASSES * D_CONV);
}

// ---------------- bilinear decoder combine ----------------------------------
__global__ void decode_kernel(const float* __restrict__ t0, const float* __restrict__ t1,
                              const float* __restrict__ ve, const float* __restrict__ Wcomb,
                              float* __restrict__ out) {
    int b = blockIdx.x, t = threadIdx.x;
    float v  = ve[(long)b * D_EMB + t];
    float a0 = t0[(long)b * D_EMB + t] * v;
    float a1 = t1[(long)b * D_EMB + t] * v;
#pragma unroll
    for (int o = 16; o; o >>= 1) {
        a0 += __shfl_down_sync(0xffffffffu, a0, o);
        a1 += __shfl_down_sync(0xffffffffu, a1, o);
    }
    __shared__ float s0[8], s1[8];
    if ((t & 31) == 0) { s0[t >> 5] = a0; s1[t >> 5] = a1; }
    __syncthreads();
    if (t == 0) {
        float d0 = 0.f, d1 = 0.f;
#pragma unroll
        for (int i = 0; i < 8; i++) { d0 += s0[i]; d1 += s1[i]; }
        s0[0] = d0; s1[0] = d1;
    }
    __syncthreads();
    if (t < CLASSES)
        out[(long)b * CLASSES + t] = Wcomb[t * 2] * s0[0] + Wcomb[t * 2 + 1] * s1[0];
}

// ---------------- launch ----------------------------------------------------
extern "C" void kernel_launch(void* const* d_in, const int* in_sizes, int n_in,
                              void* d_out, int out_size) {
    const float* user_feat = (const float*)d_in[0];
    const float* item_feat = (const float*)d_in[1];
    const int*   user_idx  = (const int*)d_in[2];
    const int*   item_idx  = (const int*)d_in[3];
    const int*   u_src     = (const int*)d_in[4];
    const int*   u_dst     = (const int*)d_in[5];
    const float* u_w       = (const float*)d_in[6];
    const int*   i_src     = (const int*)d_in[7];
    const int*   i_dst     = (const int*)d_in[8];
    const float* i_w       = (const float*)d_in[9];
    const float* W_fu      = (const float*)d_in[10];
    const float* b_fu      = (const float*)d_in[11];
    const float* W_fi      = (const float*)d_in[12];
    const float* b_fi      = (const float*)d_in[13];
    const float* W_uc      = (const float*)d_in[14];
    const float* W_ic      = (const float*)d_in[15];
    const float* bn_fu     = (const float*)d_in[16];
    const float* bn_hu     = (const float*)d_in[17];
    const float* bn_fi     = (const float*)d_in[18];
    const float* bn_hi     = (const float*)d_in[19];
    const float* W2_fu     = (const float*)d_in[20];
    const float* W2_hu     = (const float*)d_in[21];
    const float* W2_fi     = (const float*)d_in[22];
    const float* W2_hi     = (const float*)d_in[23];
    const float* Wdec      = (const float*)d_in[24];
    const float* Wcomb     = (const float*)d_in[25];
    float* out = (float*)d_out;

    void* p;
    cudaGetSymbolAddress(&p, g_agg); float* agg  = (float*)p;
    cudaGetSymbolAddress(&p, g_f);   float* fb   = (float*)p;
    cudaGetSymbolAddress(&p, g_h);   float* hb   = (float*)p;
    cudaGetSymbolAddress(&p, g_emb); float* emb  = (float*)p;
    cudaGetSymbolAddress(&p, g_t);   float* tdec = (float*)p;

    const int HD = CLASSES * D_CONV;  // 640

    // 0) fp16 feature tables (independent of sort chain)
    {
        long q = 2L * N_USERS * N_FEAT / 4;
        tofp16_kernel<<<(int)((q + 255) / 256), 256>>>(user_feat, item_feat);
    }

    // 1) edge counting-sort by dst (per segment), 4-edge ILP
    zero_cnt_kernel<<<(SEGS * BATCH + 255) / 256, 256>>>();
    int qblocks = (EQUARTER + 255) / 256;
    hist_kernel<<<qblocks, 256>>>(u_dst, i_dst);
    scan_kernel<<<SEGS, 1024>>>();
    scatter_kernel<<<qblocks, 256>>>(u_src, u_dst, u_w, i_src, i_dst, i_w);

    // 2) per-bucket weighted aggregation (fp16 gathers, fp32 accumulate)
    agg_kernel<<<dim3(BATCH, SEGS), 256>>>();

    // 3) f projections: gather + GEMM + bias + BN + relu (dual-z: user/item)
    gemm_dual<1><<<dim3(1, 64, 2), 256>>>(
        user_feat, item_feat, nullptr, nullptr, N_FEAT, 0, 1 << 30,
        user_idx, item_idx,
        W_fu, W_fi, nullptr, nullptr, 256,
        fb, fb + (long)BATCH * 256, 256, N_FEAT,
        b_fu, b_fi, bn_fu, bn_fi, 256);

    // 4) all 10 class projections in one launch (128-wide blocks)
    class_proj_kernel<<<dim3(1, 64, 10), 128>>>(agg, W_uc, W_ic, bn_hu, bn_hi, hb);

    // 5) fused embeddings: emb = relu([f|h] @ [W2_f; W2_h]), K = 256+640
    gemm_dual<3><<<dim3(1, 64, 2), 256>>>(
        fb, fb + (long)BATCH * 256, hb, hb + (long)BATCH * HD,
        256, HD, 256,
        nullptr, nullptr,
        W2_fu, W2_fi, W2_hu, W2_hi, D_EMB,
        emb, emb + (long)BATCH * D_EMB, D_EMB, 256 + HD,
        nullptr, nullptr, nullptr, nullptr, 0);

    // 6) bilinear decoder
    float* uemb = emb;
    float* iemb = emb + (long)BATCH * D_EMB;
    gemm_dual<0><<<dim3(1, 64, 2), 256>>>(
        uemb, uemb, nullptr, nullptr, D_EMB, 0, 1 << 30,
        nullptr, nullptr,
        Wdec, Wdec + D_EMB * D_EMB, nullptr, nullptr, D_EMB,
        tdec, tdec + (long)BATCH * D_EMB, D_EMB, D_EMB,
        nullptr, nullptr, nullptr, nullptr, 0);
    decode_kernel<<<BATCH, 256>>>(tdec, tdec + (long)BATCH * D_EMB, iemb, Wcomb, out);
}

// round 13
// speedup vs baseline: 2.7051x; 1.1943x over previous
#include <cuda_runtime.h>
#include <cuda_fp16.h>
#include <cuda_bf16.h>
#include <mma.h>
#include <cstdint>

using namespace nvcuda;

#define N_USERS  100000
#define N_ITEMS  100000
#define N_FEAT   256
#define BATCH    8192
#define CLASSES  5
#define EDGES    500000
#define D_CONV   128
#define D_EMB    256
#define SEGS     10
#define BN_EPS   1e-3f

#define ASTRIDE_H 24   // A smem row stride in halves: 16 k + 8 pad (48B rows)
#define CSTRIDE   20   // staging row stride (floats)

// ---------------- scratch ----------------------------------------------------
__device__ int    g_cnt [SEGS * BATCH];
__device__ int    g_off [SEGS * BATCH];
__device__ int2   g_ep  [SEGS * EDGES];
__device__ __half g_u16 [(long)N_USERS * N_FEAT];
__device__ __half g_i16 [(long)N_ITEMS * N_FEAT];
__device__ float  g_agg [SEGS * BATCH * N_FEAT];
__device__ float  g_f   [2 * BATCH * N_FEAT];
__device__ float  g_h   [2 * BATCH * CLASSES * D_CONV];
__device__ float  g_emb [2 * BATCH * D_EMB];
__device__ float  g_t   [2 * BATCH * D_EMB];

// ---------------- fp16 conversion of feature tables -------------------------
__global__ void tofp16_kernel(const float* __restrict__ uf, const float* __restrict__ itf) {
    long i = (long)blockIdx.x * 256 + threadIdx.x;
    const long Q = (long)N_USERS * N_FEAT / 4;
    if (i < Q) {
        float4 v = ((const float4*)uf)[i];
        __half2* o = (__half2*)g_u16;
        o[i * 2]     = __floats2half2_rn(v.x, v.y);
        o[i * 2 + 1] = __floats2half2_rn(v.z, v.w);
    } else if (i < 2 * Q) {
        long j = i - Q;
        float4 v = ((const float4*)itf)[j];
        __half2* o = (__half2*)g_i16;
        o[j * 2]     = __floats2half2_rn(v.x, v.y);
        o[j * 2 + 1] = __floats2half2_rn(v.z, v.w);
    }
}

// ---------------- counting sort of edges by dst, per segment ----------------
__global__ void zero_cnt_kernel() {
    int i = blockIdx.x * 256 + threadIdx.x;
    if (i < SEGS * BATCH) g_cnt[i] = 0;
}

#define EQUARTER (SEGS * EDGES / 4)

__global__ void hist_kernel(const int* __restrict__ udst, const int* __restrict__ idst) {
    int i = blockIdx.x * 256 + threadIdx.x;
    if (i >= EQUARTER) return;
#pragma unroll
    for (int j = 0; j < 4; j++) {
        int idx = i + j * EQUARTER;
        int seg = idx / EDGES, e = idx - seg * EDGES;
        int dst = (seg < CLASSES) ? udst[seg * EDGES + e] : idst[(seg - CLASSES) * EDGES + e];
        atomicAdd(&g_cnt[seg * BATCH + dst], 1);
    }
}

__global__ void scan_kernel() {
    int seg = blockIdx.x;
    int t = threadIdx.x;
    int base = seg * BATCH + t * 8;
    int v[8], s = 0;
#pragma unroll
    for (int j = 0; j < 8; j++) { v[j] = g_cnt[base + j]; s += v[j]; }
    __shared__ int sh[1024];
    sh[t] = s;
    __syncthreads();
    for (int off = 1; off < 1024; off <<= 1) {
        int x = (t >= off) ? sh[t - off] : 0;
        __syncthreads();
        sh[t] += x;
        __syncthreads();
    }
    int run = sh[t] - s;
#pragma unroll
    for (int j = 0; j < 8; j++) {
        g_off[base + j] = run;
        g_cnt[base + j] = run;
        run += v[j];
    }
}

__global__ void scatter_kernel(const int* __restrict__ usrc, const int* __restrict__ udst,
                               const float* __restrict__ uw,
                               const int* __restrict__ isrc, const int* __restrict__ idst,
                               const float* __restrict__ iw) {
    int i = blockIdx.x * 256 + threadIdx.x;
    if (i >= EQUARTER) return;
#pragma unroll
    for (int j = 0; j < 4; j++) {
        int idx = i + j * EQUARTER;
        int seg = idx / EDGES, e = idx - seg * EDGES;
        int src, dst; float w;
        if (seg < CLASSES) {
            int o = seg * EDGES + e;
            src = usrc[o]; dst = udst[o]; w = uw[o];
        } else {
            int o = (seg - CLASSES) * EDGES + e;
            src = isrc[o]; dst = idst[o]; w = iw[o];
        }
        int pos = atomicAdd(&g_cnt[seg * BATCH + dst], 1);
        g_ep[seg * EDGES + pos] = make_int2(src, __float_as_int(w));
    }
}

// ---------------- aggregation: fp16 feature gather --------------------------
__global__ void agg_kernel() {
    int dst = blockIdx.x;
    int seg = blockIdx.y;
    int tid  = threadIdx.x;
    int lane = tid & 31;
    int slot = tid >> 5;
    const uint4* feat = (const uint4*)((seg < CLASSES) ? g_i16 : g_u16);
    int start = g_off[seg * BATCH + dst];
    int end   = g_cnt[seg * BATCH + dst];
    const int2* ep = g_ep + seg * EDGES;

    float acc[8];
#pragma unroll
    for (int j = 0; j < 8; j++) acc[j] = 0.f;

    for (int e = start + slot; e < end; e += 8) {
        int2 p = ep[e];
        float w = __int_as_float(p.y);
        uint4 v = feat[(long)p.x * 32 + lane];
        const __half2* h = (const __half2*)&v;
#pragma unroll
        for (int q = 0; q < 4; q++) {
            float2 f = __half22float2(h[q]);
            acc[q * 2]     += w * f.x;
            acc[q * 2 + 1] += w * f.y;
        }
    }

    __shared__ float red[256][8];
#pragma unroll
    for (int j = 0; j < 8; j++) red[tid][j] = acc[j];
    __syncthreads();
    if (slot == 0) {
        float s[8];
#pragma unroll
        for (int j = 0; j < 8; j++) s[j] = red[lane][j];
#pragma unroll
        for (int k = 1; k < 8; k++)
#pragma unroll
            for (int j = 0; j < 8; j++) s[j] += red[k * 32 + lane][j];
        float4* outp = (float4*)(g_agg + ((long)seg * BATCH + dst) * N_FEAT + lane * 8);
        outp[0] = make_float4(s[0], s[1], s[2], s[3]);
        outp[1] = make_float4(s[4], s[5], s[6], s[7]);
    }
}

// ---------------- fp16 WMMA GEMM, 64x64 warp tiles, k-chunk 16 ---------------
// NW = n-warp count: block 128 x (64*NW), 64*NW threads (2*NW warps).
// warp (wm, wn) = ((warp&1)*64, (warp>>1)*64); each warp 4x4 wmma m16n16k16.
// fp16 inputs (same 11-bit mantissa as tf32), fp32 accumulate.
// EPI: 0 = none, 1 = bias+BN+relu, 2 = BN+relu, 3 = relu

template<int NW, int EPI>
__device__ __forceinline__ void gemm_core(
    __half (&As)[2][128][ASTRIDE_H], __half (&Bs)[2][16][64 * NW + 8],
    float (&stage)[2 * NW][16][CSTRIDE],
    const float* __restrict__ A1, const float* __restrict__ A2,
    int lda1, int lda2, int ksplit, const int* __restrict__ gidx,
    const float* __restrict__ B1, const float* __restrict__ B2, int ldb,
    float* __restrict__ C, int ldc, int col0, int K,
    const float* __restrict__ bias, const float* __restrict__ bnp, int bn_dim)
{
    constexpr int T = 64 * NW;          // threads
    constexpr int BST = 64 * NW + 8;    // B smem stride (halves)
    const int tid = threadIdx.x;
    const int m0 = blockIdx.y * 128, n0 = blockIdx.x * (64 * NW);
    const int warp = tid >> 5, lane = tid & 31;
    const int wm0 = (warp & 1) * 64, wn0 = (warp >> 1) * 64;

    // A loader: T=256 -> 2 threads/row, 8 k-halves each; T=128 -> 1 thread/row, 16
    const int arow = (T == 256) ? (tid & 127) : tid;
    const int ak   = (T == 256) ? ((tid >> 7) * 8) : 0;
    // B loader: 16 rows x (64*NW) cols halves; each thread 16 cols of one row
    const int brow = (T == 256) ? (tid >> 4) : (tid >> 3);
    const int bcol = (T == 256) ? ((tid & 15) * 16) : ((tid & 7) * 16);

    const float *Ap1, *Ap2 = nullptr;
    {
        int r = gidx ? gidx[m0 + arow] : (m0 + arow);
        Ap1 = A1 + (long)r * lda1;
        if (A2) Ap2 = A2 + (long)r * lda2;
    }
    const float* Bp1 = B1 + n0 + bcol;
    const float* Bp2 = B2 ? (B2 + n0 + bcol) : nullptr;

    wmma::fragment<wmma::accumulator, 16, 16, 16, float> facc[4][4];
#pragma unroll
    for (int i = 0; i < 4; i++)
#pragma unroll
        for (int j = 0; j < 4; j++) wmma::fill_fragment(facc[i][j], 0.f);

    float a_st[(T == 256) ? 8 : 16], b_st[16];

    auto load_chunk = [&](int k0) {
        const float *ap, *bp;
        if (k0 < ksplit) {
            ap = Ap1 + k0 + ak;
            bp = Bp1 + (long)(k0 + brow) * ldb;
        } else {
            ap = Ap2 + (k0 - ksplit) + ak;
            bp = Bp2 + (long)(k0 - ksplit + brow) * ldb;
        }
#pragma unroll
        for (int q = 0; q < ((T == 256) ? 2 : 4); q++) {
            float4 x = *(const float4*)(ap + q * 4);
            a_st[q * 4 + 0] = x.x; a_st[q * 4 + 1] = x.y;
            a_st[q * 4 + 2] = x.z; a_st[q * 4 + 3] = x.w;
        }
#pragma unroll
        for (int q = 0; q < 4; q++) {
            float4 u = *(const float4*)(bp + q * 4);
            b_st[q * 4 + 0] = u.x; b_st[q * 4 + 1] = u.y;
            b_st[q * 4 + 2] = u.z; b_st[q * 4 + 3] = u.w;
        }
    };

    auto store_chunk = [&](int buf) {
        {
            __half2 h[(T == 256) ? 4 : 8];
#pragma unroll
            for (int q = 0; q < ((T == 256) ? 4 : 8); q++)
                h[q] = __floats2half2_rn(a_st[q * 2], a_st[q * 2 + 1]);
            *(uint4*)&As[buf][arow][ak] = *(uint4*)&h[0];
            if (T == 128)
                *(uint4*)&As[buf][arow][8] = *(uint4*)&h[4];
        }
        {
            __half2 h[8];
#pragma unroll
            for (int q = 0; q < 8; q++)
                h[q] = __floats2half2_rn(b_st[q * 2], b_st[q * 2 + 1]);
            *(uint4*)&Bs[buf][brow][bcol]     = *(uint4*)&h[0];
            *(uint4*)&Bs[buf][brow][bcol + 8] = *(uint4*)&h[4];
        }
    };

    const int nc = K / 16;
    load_chunk(0);
    store_chunk(0);
    __syncthreads();

    for (int ch = 0; ch < nc; ch++) {
        int cur = ch & 1;
        if (ch + 1 < nc) load_chunk((ch + 1) * 16);
        wmma::fragment<wmma::matrix_b, 16, 16, 16, __half, wmma::row_major> fb[4];
#pragma unroll
        for (int na = 0; na < 4; na++)
            wmma::load_matrix_sync(fb[na], &Bs[cur][0][wn0 + na * 16], BST);
#pragma unroll
        for (int ma = 0; ma < 4; ma++) {
            wmma::fragment<wmma::matrix_a, 16, 16, 16, __half, wmma::row_major> fa;
            wmma::load_matrix_sync(fa, &As[cur][wm0 + ma * 16][0], ASTRIDE_H);
#pragma unroll
            for (int na = 0; na < 4; na++)
                wmma::mma_sync(facc[ma][na], fa, fb[na], facc[ma][na]);
        }
        if (ch + 1 < nc) {
            store_chunk(cur ^ 1);
            __syncthreads();
        }
    }

    // epilogue: stage each 16x16 tile through smem, apply post-ops, store
    __syncthreads();
    const int srow = lane >> 1;
    const int scol = (lane & 1) * 8;
#pragma unroll
    for (int ma = 0; ma < 4; ma++) {
#pragma unroll
        for (int na = 0; na < 4; na++) {
            wmma::store_matrix_sync(&stage[warp][0][0], facc[ma][na], CSTRIDE, wmma::mem_row_major);
            __syncwarp();
            int r  = m0 + wm0 + ma * 16 + srow;
            int cb = n0 + wn0 + na * 16 + scol;
            float x[8];
#pragma unroll
            for (int j = 0; j < 8; j++) {
                float v = stage[warp][srow][scol + j];
                int cgl = cb + j;
                int cg  = col0 + cgl;
                if (EPI == 1) v += bias[cgl];
                if (EPI == 1 || EPI == 2) {
                    float gm = bnp[cg];
                    float be = bnp[bn_dim + cg];
                    float mn = bnp[2 * bn_dim + cg];
                    float vr = bnp[3 * bn_dim + cg];
                    v = gm * (v - mn) * rsqrtf(vr + BN_EPS) + be;
                    v = fmaxf(v, 0.f);
                }
                if (EPI == 3) v = fmaxf(v, 0.f);
                x[j] = v;
            }
            float* cp = C + (long)r * ldc + col0 + cb;
            *(float4*)(cp)     = make_float4(x[0], x[1], x[2], x[3]);
            *(float4*)(cp + 4) = make_float4(x[4], x[5], x[6], x[7]);
            __syncwarp();
        }
    }
}

// wide kernel: N-tile 256, 256 threads, dual-z parameter sets
template<int EPI>
__global__ void __launch_bounds__(256, 1) gemm_dual(
    const float* A1a, const float* A1b, const float* A2a, const float* A2b,
    int lda1, int lda2, int ksplit,
    const int* gx0, const int* gx1,
    const float* B1a, const float* B1b, const float* B2a, const float* B2b, int ldb,
    float* C0, float* C1, int ldc, int K,
    const float* bias0, const float* bias1,
    const float* bn0, const float* bn1, int bn_dim)
{
    __shared__ __half As[2][128][ASTRIDE_H];
    __shared__ __half Bs[2][16][264];
    __shared__ float  St[8][16][CSTRIDE];
    if (blockIdx.z == 0)
        gemm_core<4, EPI>(As, Bs, St, A1a, A2a, lda1, lda2, ksplit, gx0, B1a, B2a, ldb,
                          C0, ldc, 0, K, bias0, bn0, bn_dim);
    else
        gemm_core<4, EPI>(As, Bs, St, A1b, A2b, lda1, lda2, ksplit, gx1, B1b, B2b, ldb,
                          C1, ldc, 0, K, bias1, bn1, bn_dim);
}

// narrow kernel: N-tile 128, 128 threads, blockIdx.z = seg (class projections)
__global__ void __launch_bounds__(128, 1) class_proj_kernel(
    const float* __restrict__ agg,
    const float* __restrict__ Wuc, const float* __restrict__ Wic,
    const float* __restrict__ bn_hu, const float* __restrict__ bn_hi,
    float* __restrict__ hb)
{
    __shared__ __half As[2][128][ASTRIDE_H];
    __shared__ __half Bs[2][16][136];
    __shared__ float  St[4][16][CSTRIDE];
    int seg = blockIdx.z;
    int side = seg / CLASSES, c = seg % CLASSES;
    const float* A  = agg + (long)seg * BATCH * N_FEAT;
    const float* B  = (side ? Wic : Wuc) + (long)c * N_FEAT * D_CONV;
    const float* bn = side ? bn_hi : bn_hu;
    float* C = hb + (long)side * BATCH * (CLASSES * D_CONV);
    gemm_core<2, 2>(As, Bs, St, A, nullptr, N_FEAT, 0, 1 << 30, nullptr, B, nullptr, D_CONV,
                    C, CLASSES * D_CONV, c * D_CONV, N_FEAT, nullptr, bn, CLASSES * D_CONV);
}

// ---------------- bilinear decoder combine ----------------------------------
__global__ void decode_kernel(const float* __restrict__ t0, const float* __restrict__ t1,
                              const float* __restrict__ ve, const float* __restrict__ Wcomb,
                              float* __restrict__ out) {
    int b = blockIdx.x, t = threadIdx.x;
    float v  = ve[(long)b * D_EMB + t];
    float a0 = t0[(long)b * D_EMB + t] * v;
    float a1 = t1[(long)b * D_EMB + t] * v;
#pragma unroll
    for (int o = 16; o; o >>= 1) {
        a0 += __shfl_down_sync(0xffffffffu, a0, o);
        a1 += __shfl_down_sync(0xffffffffu, a1, o);
    }
    __shared__ float s0[8], s1[8];
    if ((t & 31) == 0) { s0[t >> 5] = a0; s1[t >> 5] = a1; }
    __syncthreads();
    if (t == 0) {
        float d0 = 0.f, d1 = 0.f;
#pragma unroll
        for (int i = 0; i < 8; i++) { d0 += s0[i]; d1 += s1[i]; }
        s0[0] = d0; s1[0] = d1;
    }
    __syncthreads();
    if (t < CLASSES)
        out[(long)b * CLASSES + t] = Wcomb[t * 2] * s0[0] + Wcomb[t * 2 + 1] * s1[0];
}

// ---------------- launch ----------------------------------------------------
extern "C" void kernel_launch(void* const* d_in, const int* in_sizes, int n_in,
                              void* d_out, int out_size) {
    const float* user_feat = (const float*)d_in[0];
    const float* item_feat = (const float*)d_in[1];
    const int*   user_idx  = (const int*)d_in[2];
    const int*   item_idx  = (const int*)d_in[3];
    const int*   u_src     = (const int*)d_in[4];
    const int*   u_dst     = (const int*)d_in[5];
    const float* u_w       = (const float*)d_in[6];
    const int*   i_src     = (const int*)d_in[7];
    const int*   i_dst     = (const int*)d_in[8];
    const float* i_w       = (const float*)d_in[9];
    const float* W_fu      = (const float*)d_in[10];
    const float* b_fu      = (const float*)d_in[11];
    const float* W_fi      = (const float*)d_in[12];
    const float* b_fi      = (const float*)d_in[13];
    const float* W_uc      = (const float*)d_in[14];
    const float* W_ic      = (const float*)d_in[15];
    const float* bn_fu     = (const float*)d_in[16];
    const float* bn_hu     = (const float*)d_in[17];
    const float* bn_fi     = (const float*)d_in[18];
    const float* bn_hi     = (const float*)d_in[19];
    const float* W2_fu     = (const float*)d_in[20];
    const float* W2_hu     = (const float*)d_in[21];
    const float* W2_fi     = (const float*)d_in[22];
    const float* W2_hi     = (const float*)d_in[23];
    const float* Wdec      = (const float*)d_in[24];
    const float* Wcomb     = (const float*)d_in[25];
    float* out = (float*)d_out;

    void* p;
    cudaGetSymbolAddress(&p, g_agg); float* agg  = (float*)p;
    cudaGetSymbolAddress(&p, g_f);   float* fb   = (float*)p;
    cudaGetSymbolAddress(&p, g_h);   float* hb   = (float*)p;
    cudaGetSymbolAddress(&p, g_emb); float* emb  = (float*)p;
    cudaGetSymbolAddress(&p, g_t);   float* tdec = (float*)p;

    const int HD = CLASSES * D_CONV;  // 640

    // 0) fp16 feature tables (independent of sort chain)
    {
        long q = 2L * N_USERS * N_FEAT / 4;
        tofp16_kernel<<<(int)((q + 255) / 256), 256>>>(user_feat, item_feat);
    }

    // 1) edge counting-sort by dst (per segment), 4-edge ILP
    zero_cnt_kernel<<<(SEGS * BATCH + 255) / 256, 256>>>();
    int qblocks = (EQUARTER + 255) / 256;
    hist_kernel<<<qblocks, 256>>>(u_dst, i_dst);
    scan_kernel<<<SEGS, 1024>>>();
    scatter_kernel<<<qblocks, 256>>>(u_src, u_dst, u_w, i_src, i_dst, i_w);

    // 2) per-bucket weighted aggregation (fp16 gathers, fp32 accumulate)
    agg_kernel<<<dim3(BATCH, SEGS), 256>>>();

    // 3) f projections: gather + GEMM + bias + BN + relu (dual-z: user/item)
    gemm_dual<1><<<dim3(1, 64, 2), 256>>>(
        user_feat, item_feat, nullptr, nullptr, N_FEAT, 0, 1 << 30,
        user_idx, item_idx,
        W_fu, W_fi, nullptr, nullptr, 256,
        fb, fb + (long)BATCH * 256, 256, N_FEAT,
        b_fu, b_fi, bn_fu, bn_fi, 256);

    // 4) all 10 class projections in one launch (128-wide blocks)
    class_proj_kernel<<<dim3(1, 64, 10), 128>>>(agg, W_uc, W_ic, bn_hu, bn_hi, hb);

    // 5) fused embeddings: emb = relu([f|h] @ [W2_f; W2_h]), K = 256+640
    gemm_dual<3><<<dim3(1, 64, 2), 256>>>(
        fb, fb + (long)BATCH * 256, hb, hb + (long)BATCH * HD,
        256, HD, 256,
        nullptr, nullptr,
        W2_fu, W2_fi, W2_hu, W2_hi, D_EMB,
        emb, emb + (long)BATCH * D_EMB, D_EMB, 256 + HD,
        nullptr, nullptr, nullptr, nullptr, 0);

    // 6) bilinear decoder
    float* uemb = emb;
    float* iemb = emb + (long)BATCH * D_EMB;
    gemm_dual<0><<<dim3(1, 64, 2), 256>>>(
        uemb, uemb, nullptr, nullptr, D_EMB, 0, 1 << 30,
        nullptr, nullptr,
        Wdec, Wdec + D_EMB * D_EMB, nullptr, nullptr, D_EMB,
        tdec, tdec + (long)BATCH * D_EMB, D_EMB, D_EMB,
        nullptr, nullptr, nullptr, nullptr, 0);
    decode_kernel<<<BATCH, 256>>>(tdec, tdec + (long)BATCH * D_EMB, iemb, Wcomb, out);
}

// round 14
// speedup vs baseline: 2.8365x; 1.0486x over previous
#include <cuda_runtime.h>
#include <cuda_fp16.h>
#include <cuda_bf16.h>
#include <mma.h>
#include <cstdint>

using namespace nvcuda;

#define N_USERS  100000
#define N_ITEMS  100000
#define N_FEAT   256
#define BATCH    8192
#define CLASSES  5
#define EDGES    500000
#define D_CONV   128
#define D_EMB    256
#define SEGS     10
#define BN_EPS   1e-3f

#define ASTRIDE_H 24   // A smem row stride in halves
#define BSTRIDE_H 136  // B smem row stride in halves
#define CSTRIDE   20   // staging row stride (floats)

// ---------------- scratch ----------------------------------------------------
__device__ int    g_cnt [SEGS * BATCH];
__device__ int    g_off [SEGS * BATCH];
__device__ int2   g_ep  [SEGS * EDGES];
__device__ __half g_u16 [(long)N_USERS * N_FEAT];
__device__ __half g_i16 [(long)N_ITEMS * N_FEAT];
__device__ float  g_agg [SEGS * BATCH * N_FEAT];
__device__ float  g_f   [2 * BATCH * N_FEAT];
__device__ float  g_h   [2 * BATCH * CLASSES * D_CONV];
__device__ float  g_emb [2 * BATCH * D_EMB];
__device__ float  g_t   [2 * BATCH * D_EMB];

// ---------------- fp16 conversion of feature tables (+ counter zeroing) -----
__global__ void tofp16_kernel(const float* __restrict__ uf, const float* __restrict__ itf) {
    long i = (long)blockIdx.x * 256 + threadIdx.x;
    if (i < SEGS * BATCH) g_cnt[i] = 0;
    const long Q = (long)N_USERS * N_FEAT / 4;
    if (i < Q) {
        float4 v = ((const float4*)uf)[i];
        __half2* o = (__half2*)g_u16;
        o[i * 2]     = __floats2half2_rn(v.x, v.y);
        o[i * 2 + 1] = __floats2half2_rn(v.z, v.w);
    } else if (i < 2 * Q) {
        long j = i - Q;
        float4 v = ((const float4*)itf)[j];
        __half2* o = (__half2*)g_i16;
        o[j * 2]     = __floats2half2_rn(v.x, v.y);
        o[j * 2 + 1] = __floats2half2_rn(v.z, v.w);
    }
}

// ---------------- counting sort of edges by dst, per segment ----------------
#define EQUARTER (SEGS * EDGES / 4)

__global__ void hist_kernel(const int* __restrict__ udst, const int* __restrict__ idst) {
    int i = blockIdx.x * 256 + threadIdx.x;
    if (i >= EQUARTER) return;
#pragma unroll
    for (int j = 0; j < 4; j++) {
        int idx = i + j * EQUARTER;
        int seg = idx / EDGES, e = idx - seg * EDGES;
        int dst = (seg < CLASSES) ? udst[seg * EDGES + e] : idst[(seg - CLASSES) * EDGES + e];
        atomicAdd(&g_cnt[seg * BATCH + dst], 1);
    }
}

__global__ void scan_kernel() {
    int seg = blockIdx.x;
    int t = threadIdx.x;
    int base = seg * BATCH + t * 8;
    int v[8], s = 0;
#pragma unroll
    for (int j = 0; j < 8; j++) { v[j] = g_cnt[base + j]; s += v[j]; }
    __shared__ int sh[1024];
    sh[t] = s;
    __syncthreads();
    for (int off = 1; off < 1024; off <<= 1) {
        int x = (t >= off) ? sh[t - off] : 0;
        __syncthreads();
        sh[t] += x;
        __syncthreads();
    }
    int run = sh[t] - s;
#pragma unroll
    for (int j = 0; j < 8; j++) {
        g_off[base + j] = run;
        g_cnt[base + j] = run;
        run += v[j];
    }
}

__global__ void scatter_kernel(const int* __restrict__ usrc, const int* __restrict__ udst,
                               const float* __restrict__ uw,
                               const int* __restrict__ isrc, const int* __restrict__ idst,
                               const float* __restrict__ iw) {
    int i = blockIdx.x * 256 + threadIdx.x;
    if (i >= EQUARTER) return;
#pragma unroll
    for (int j = 0; j < 4; j++) {
        int idx = i + j * EQUARTER;
        int seg = idx / EDGES, e = idx - seg * EDGES;
        int src, dst; float w;
        if (seg < CLASSES) {
            int o = seg * EDGES + e;
            src = usrc[o]; dst = udst[o]; w = uw[o];
        } else {
            int o = (seg - CLASSES) * EDGES + e;
            src = isrc[o]; dst = idst[o]; w = iw[o];
        }
        int pos = atomicAdd(&g_cnt[seg * BATCH + dst], 1);
        g_ep[seg * EDGES + pos] = make_int2(src, __float_as_int(w));
    }
}

// ---------------- aggregation: fp16 feature gather --------------------------
__global__ void agg_kernel() {
    int dst = blockIdx.x;
    int seg = blockIdx.y;
    int tid  = threadIdx.x;
    int lane = tid & 31;
    int slot = tid >> 5;
    const uint4* feat = (const uint4*)((seg < CLASSES) ? g_i16 : g_u16);
    int start = g_off[seg * BATCH + dst];
    int end   = g_cnt[seg * BATCH + dst];
    const int2* ep = g_ep + seg * EDGES;

    float acc[8];
#pragma unroll
    for (int j = 0; j < 8; j++) acc[j] = 0.f;

    for (int e = start + slot; e < end; e += 8) {
        int2 p = ep[e];
        float w = __int_as_float(p.y);
        uint4 v = feat[(long)p.x * 32 + lane];
        const __half2* h = (const __half2*)&v;
#pragma unroll
        for (int q = 0; q < 4; q++) {
            float2 f = __half22float2(h[q]);
            acc[q * 2]     += w * f.x;
            acc[q * 2 + 1] += w * f.y;
        }
    }

    __shared__ float red[256][8];
#pragma unroll
    for (int j = 0; j < 8; j++) red[tid][j] = acc[j];
    __syncthreads();
    if (slot == 0) {
        float s[8];
#pragma unroll
        for (int j = 0; j < 8; j++) s[j] = red[lane][j];
#pragma unroll
        for (int k = 1; k < 8; k++)
#pragma unroll
            for (int j = 0; j < 8; j++) s[j] += red[k * 32 + lane][j];
        float4* outp = (float4*)(g_agg + ((long)seg * BATCH + dst) * N_FEAT + lane * 8);
        outp[0] = make_float4(s[0], s[1], s[2], s[3]);
        outp[1] = make_float4(s[4], s[5], s[6], s[7]);
    }
}

// ---------------- fp16 WMMA GEMM core: 128-thr block, 128x128 tile ----------
// 4 warps in 2m x 2n grid; each warp 64x64 via 4x4 wmma m16n16k16 tiles.
// EPI: 0 = none (direct store), 1 = bias+BN+relu, 2 = BN+relu, 3 = relu (direct)

template<int EPI>
__device__ __forceinline__ void gemm_core128(
    __half (&As)[2][128][ASTRIDE_H], __half (&Bs)[2][16][BSTRIDE_H],
    float (&stage)[4][16][CSTRIDE],
    const float* __restrict__ A1, const float* __restrict__ A2,
    int lda1, int lda2, int ksplit, const int* __restrict__ gidx,
    const float* __restrict__ B1, const float* __restrict__ B2, int ldb,
    float* __restrict__ C, int ldc, int col0, int K,
    const float* __restrict__ bias, const float* __restrict__ bnp, int bn_dim)
{
    const int tid = threadIdx.x;
    const int m0 = blockIdx.y * 128, n0 = blockIdx.x * 128;
    const int warp = tid >> 5, lane = tid & 31;
    const int wm0 = (warp & 1) * 64, wn0 = (warp >> 1) * 64;

    const int arow = tid;                       // 1 thread per A row, 16 halves
    const int brow = tid >> 3, bcol = (tid & 7) * 16;

    const float *Ap1, *Ap2 = nullptr;
    {
        int r = gidx ? gidx[m0 + arow] : (m0 + arow);
        Ap1 = A1 + (long)r * lda1;
        if (A2) Ap2 = A2 + (long)r * lda2;
    }
    const float* Bp1 = B1 + n0 + bcol;
    const float* Bp2 = B2 ? (B2 + n0 + bcol) : nullptr;

    wmma::fragment<wmma::accumulator, 16, 16, 16, float> facc[4][4];
#pragma unroll
    for (int i = 0; i < 4; i++)
#pragma unroll
        for (int j = 0; j < 4; j++) wmma::fill_fragment(facc[i][j], 0.f);

    float a_st[16], b_st[16];

    auto load_chunk = [&](int k0) {
        const float *ap, *bp;
        if (k0 < ksplit) {
            ap = Ap1 + k0;
            bp = Bp1 + (long)(k0 + brow) * ldb;
        } else {
            ap = Ap2 + (k0 - ksplit);
            bp = Bp2 + (long)(k0 - ksplit + brow) * ldb;
        }
#pragma unroll
        for (int q = 0; q < 4; q++) {
            float4 x = *(const float4*)(ap + q * 4);
            a_st[q * 4 + 0] = x.x; a_st[q * 4 + 1] = x.y;
            a_st[q * 4 + 2] = x.z; a_st[q * 4 + 3] = x.w;
        }
#pragma unroll
        for (int q = 0; q < 4; q++) {
            float4 u = *(const float4*)(bp + q * 4);
            b_st[q * 4 + 0] = u.x; b_st[q * 4 + 1] = u.y;
            b_st[q * 4 + 2] = u.z; b_st[q * 4 + 3] = u.w;
        }
    };

    auto store_chunk = [&](int buf) {
        __half2 ha[8];
#pragma unroll
        for (int q = 0; q < 8; q++)
            ha[q] = __floats2half2_rn(a_st[q * 2], a_st[q * 2 + 1]);
        *(uint4*)&As[buf][arow][0] = *(uint4*)&ha[0];
        *(uint4*)&As[buf][arow][8] = *(uint4*)&ha[4];
        __half2 hb[8];
#pragma unroll
        for (int q = 0; q < 8; q++)
            hb[q] = __floats2half2_rn(b_st[q * 2], b_st[q * 2 + 1]);
        *(uint4*)&Bs[buf][brow][bcol]     = *(uint4*)&hb[0];
        *(uint4*)&Bs[buf][brow][bcol + 8] = *(uint4*)&hb[4];
    };

    const int nc = K / 16;
    load_chunk(0);
    store_chunk(0);
    __syncthreads();

    for (int ch = 0; ch < nc; ch++) {
        int cur = ch & 1;
        if (ch + 1 < nc) load_chunk((ch + 1) * 16);
        wmma::fragment<wmma::matrix_b, 16, 16, 16, __half, wmma::row_major> fb[4];
#pragma unroll
        for (int na = 0; na < 4; na++)
            wmma::load_matrix_sync(fb[na], &Bs[cur][0][wn0 + na * 16], BSTRIDE_H);
#pragma unroll
        for (int ma = 0; ma < 4; ma++) {
            wmma::fragment<wmma::matrix_a, 16, 16, 16, __half, wmma::row_major> fa;
            wmma::load_matrix_sync(fa, &As[cur][wm0 + ma * 16][0], ASTRIDE_H);
#pragma unroll
            for (int na = 0; na < 4; na++)
                wmma::mma_sync(facc[ma][na], fa, fb[na], facc[ma][na]);
        }
        if (ch + 1 < nc) {
            store_chunk(cur ^ 1);
            __syncthreads();
        }
    }

    if (EPI == 0 || EPI == 3) {
        // direct store: post-op in fragment registers, no staging
#pragma unroll
        for (int ma = 0; ma < 4; ma++)
#pragma unroll
            for (int na = 0; na < 4; na++) {
                if (EPI == 3) {
#pragma unroll
                    for (int e = 0; e < facc[ma][na].num_elements; e++)
                        facc[ma][na].x[e] = fmaxf(facc[ma][na].x[e], 0.f);
                }
                float* cp = C + (long)(m0 + wm0 + ma * 16) * ldc
                              + col0 + n0 + wn0 + na * 16;
                wmma::store_matrix_sync(cp, facc[ma][na], ldc, wmma::mem_row_major);
            }
    } else {
        __syncthreads();
        const int srow = lane >> 1;
        const int scol = (lane & 1) * 8;
#pragma unroll
        for (int ma = 0; ma < 4; ma++) {
#pragma unroll
            for (int na = 0; na < 4; na++) {
                wmma::store_matrix_sync(&stage[warp][0][0], facc[ma][na], CSTRIDE,
                                        wmma::mem_row_major);
                __syncwarp();
                int r  = m0 + wm0 + ma * 16 + srow;
                int cb = n0 + wn0 + na * 16 + scol;
                float x[8];
#pragma unroll
                for (int j = 0; j < 8; j++) {
                    float v = stage[warp][srow][scol + j];
                    int cgl = cb + j;
                    int cg  = col0 + cgl;
                    if (EPI == 1) v += bias[cgl];
                    float gm = bnp[cg];
                    float be = bnp[bn_dim + cg];
                    float mn = bnp[2 * bn_dim + cg];
                    float vr = bnp[3 * bn_dim + cg];
                    v = gm * (v - mn) * rsqrtf(vr + BN_EPS) + be;
                    x[j] = fmaxf(v, 0.f);
                }
                float* cp = C + (long)r * ldc + col0 + cb;
                *(float4*)(cp)     = make_float4(x[0], x[1], x[2], x[3]);
                *(float4*)(cp + 4) = make_float4(x[4], x[5], x[6], x[7]);
                __syncwarp();
            }
        }
    }
}

// ---- launch A: f projections (z=0,1) + class projections (z=2..11) ---------
__global__ void __launch_bounds__(128) proj_batch_kernel(
    const float* __restrict__ user_feat, const float* __restrict__ item_feat,
    const int* __restrict__ user_idx, const int* __restrict__ item_idx,
    const float* __restrict__ W_fu, const float* __restrict__ b_fu, const float* __restrict__ bn_fu,
    const float* __restrict__ W_fi, const float* __restrict__ b_fi, const float* __restrict__ bn_fi,
    const float* __restrict__ agg,
    const float* __restrict__ Wuc, const float* __restrict__ Wic,
    const float* __restrict__ bn_hu, const float* __restrict__ bn_hi,
    float* __restrict__ fb, float* __restrict__ hb)
{
    __shared__ __half As[2][128][ASTRIDE_H];
    __shared__ __half Bs[2][16][BSTRIDE_H];
    __shared__ float  St[4][16][CSTRIDE];
    int z = blockIdx.z;
    if (z < 2) {
        const float* A   = z ? item_feat : user_feat;
        const int*   gx  = z ? item_idx  : user_idx;
        const float* B   = z ? W_fi  : W_fu;
        const float* bi  = z ? b_fi  : b_fu;
        const float* bn  = z ? bn_fi : bn_fu;
        float* C = fb + (long)z * BATCH * 256;
        gemm_core128<1>(As, Bs, St, A, nullptr, N_FEAT, 0, 1 << 30, gx,
                        B, nullptr, 256, C, 256, 0, N_FEAT, bi, bn, 256);
    } else {
        if (blockIdx.x) return;   // class proj is N=128
        int seg = z - 2;
        int side = seg / CLASSES, c = seg % CLASSES;
        const float* A  = agg + (long)seg * BATCH * N_FEAT;
        const float* B  = (side ? Wic : Wuc) + (long)c * N_FEAT * D_CONV;
        const float* bn = side ? bn_hi : bn_hu;
        float* C = hb + (long)side * BATCH * (CLASSES * D_CONV);
        gemm_core128<2>(As, Bs, St, A, nullptr, N_FEAT, 0, 1 << 30, nullptr,
                        B, nullptr, D_CONV, C, CLASSES * D_CONV, c * D_CONV,
                        N_FEAT, nullptr, bn, CLASSES * D_CONV);
    }
}

// ---- launch B: embeddings (fused concat GEMM, relu, direct store) ----------
__global__ void __launch_bounds__(128) emb_kernel(
    const float* __restrict__ fb, const float* __restrict__ hb,
    const float* __restrict__ W2_fu, const float* __restrict__ W2_hu,
    const float* __restrict__ W2_fi, const float* __restrict__ W2_hi,
    float* __restrict__ emb)
{
    __shared__ __half As[2][128][ASTRIDE_H];
    __shared__ __half Bs[2][16][BSTRIDE_H];
    __shared__ float  St[4][16][CSTRIDE];
    const int HD = CLASSES * D_CONV;
    int z = blockIdx.z;
    const float* A1 = fb + (long)z * BATCH * 256;
    const float* A2 = hb + (long)z * BATCH * HD;
    const float* B1 = z ? W2_fi : W2_fu;
    const float* B2 = z ? W2_hi : W2_hu;
    float* C = emb + (long)z * BATCH * D_EMB;
    gemm_core128<3>(As, Bs, St, A1, A2, 256, HD, 256, nullptr,
                    B1, B2, D_EMB, C, D_EMB, 0, 256 + HD, nullptr, nullptr, 0);
}

// ---- launch C: decoder t_k = user_emb @ Wdec[k] -----------------------------
__global__ void __launch_bounds__(128) dec_kernel(
    const float* __restrict__ uemb, const float* __restrict__ Wdec,
    float* __restrict__ tdec)
{
    __shared__ __half As[2][128][ASTRIDE_H];
    __shared__ __half Bs[2][16][BSTRIDE_H];
    __shared__ float  St[4][16][CSTRIDE];
    int z = blockIdx.z;
    gemm_core128<0>(As, Bs, St, uemb, nullptr, D_EMB, 0, 1 << 30, nullptr,
                    Wdec + (long)z * D_EMB * D_EMB, nullptr, D_EMB,
                    tdec + (long)z * BATCH * D_EMB, D_EMB, 0, D_EMB,
                    nullptr, nullptr, 0);
}

// ---------------- bilinear decoder combine ----------------------------------
__global__ void decode_kernel(const float* __restrict__ t0, const float* __restrict__ t1,
                              const float* __restrict__ ve, const float* __restrict__ Wcomb,
                              float* __restrict__ out) {
    int b = blockIdx.x, t = threadIdx.x;
    float v  = ve[(long)b * D_EMB + t];
    float a0 = t0[(long)b * D_EMB + t] * v;
    float a1 = t1[(long)b * D_EMB + t] * v;
#pragma unroll
    for (int o = 16; o; o >>= 1) {
        a0 += __shfl_down_sync(0xffffffffu, a0, o);
        a1 += __shfl_down_sync(0xffffffffu, a1, o);
    }
    __shared__ float s0[8], s1[8];
    if ((t & 31) == 0) { s0[t >> 5] = a0; s1[t >> 5] = a1; }
    __syncthreads();
    if (t == 0) {
        float d0 = 0.f, d1 = 0.f;
#pragma unroll
        for (int i = 0; i < 8; i++) { d0 += s0[i]; d1 += s1[i]; }
        s0[0] = d0; s1[0] = d1;
    }
    __syncthreads();
    if (t < CLASSES)
        out[(long)b * CLASSES + t] = Wcomb[t * 2] * s0[0] + Wcomb[t * 2 + 1] * s1[0];
}

// ---------------- launch ----------------------------------------------------
extern "C" void kernel_launch(void* const* d_in, const int* in_sizes, int n_in,
                              void* d_out, int out_size) {
    const float* user_feat = (const float*)d_in[0];
    const float* item_feat = (const float*)d_in[1];
    const int*   user_idx  = (const int*)d_in[2];
    const int*   item_idx  = (const int*)d_in[3];
    const int*   u_src     = (const int*)d_in[4];
    const int*   u_dst     = (const int*)d_in[5];
    const float* u_w       = (const float*)d_in[6];
    const int*   i_src     = (const int*)d_in[7];
    const int*   i_dst     = (const int*)d_in[8];
    const float* i_w       = (const float*)d_in[9];
    const float* W_fu      = (const float*)d_in[10];
    const float* b_fu      = (const float*)d_in[11];
    const float* W_fi      = (const float*)d_in[12];
    const float* b_fi      = (const float*)d_in[13];
    const float* W_uc      = (const float*)d_in[14];
    const float* W_ic      = (const float*)d_in[15];
    const float* bn_fu     = (const float*)d_in[16];
    const float* bn_hu     = (const float*)d_in[17];
    const float* bn_fi     = (const float*)d_in[18];
    const float* bn_hi     = (const float*)d_in[19];
    const float* W2_fu     = (const float*)d_in[20];
    const float* W2_hu     = (const float*)d_in[21];
    const float* W2_fi     = (const float*)d_in[22];
    const float* W2_hi     = (const float*)d_in[23];
    const float* Wdec      = (const float*)d_in[24];
    const float* Wcomb     = (const float*)d_in[25];
    float* out = (float*)d_out;

    void* p;
    cudaGetSymbolAddress(&p, g_agg); float* agg  = (float*)p;
    cudaGetSymbolAddress(&p, g_f);   float* fb   = (float*)p;
    cudaGetSymbolAddress(&p, g_h);   float* hb   = (float*)p;
    cudaGetSymbolAddress(&p, g_emb); float* emb  = (float*)p;
    cudaGetSymbolAddress(&p, g_t);   float* tdec = (float*)p;

    // 0) fp16 feature tables + counter zeroing (one launch)
    {
        long q = 2L * N_USERS * N_FEAT / 4;
        tofp16_kernel<<<(int)((q + 255) / 256), 256>>>(user_feat, item_feat);
    }

    // 1) edge counting-sort by dst (per segment), 4-edge ILP
    int qblocks = (EQUARTER + 255) / 256;
    hist_kernel<<<qblocks, 256>>>(u_dst, i_dst);
    scan_kernel<<<SEGS, 1024>>>();
    scatter_kernel<<<qblocks, 256>>>(u_src, u_dst, u_w, i_src, i_dst, i_w);

    // 2) per-bucket weighted aggregation (fp16 gathers, fp32 accumulate)
    agg_kernel<<<dim3(BATCH, SEGS), 256>>>();

    // 3+4) f projections + all class projections, one launch
    proj_batch_kernel<<<dim3(2, 64, 12), 128>>>(
        user_feat, item_feat, user_idx, item_idx,
        W_fu, b_fu, bn_fu, W_fi, b_fi, bn_fi,
        agg, W_uc, W_ic, bn_hu, bn_hi, fb, hb);

    // 5) embeddings: emb = relu([f|h] @ [W2_f; W2_h])
    emb_kernel<<<dim3(2, 64, 2), 128>>>(fb, hb, W2_fu, W2_hu, W2_fi, W2_hi, emb);

    // 6) bilinear decoder
    float* uemb = emb;
    float* iemb = emb + (long)BATCH * D_EMB;
    dec_kernel<<<dim3(2, 64, 2), 128>>>(uemb, Wdec, tdec);
    decode_kernel<<<BATCH, 256>>>(tdec, tdec + (long)BATCH * D_EMB, iemb, Wcomb, out);
}